// round 15
// baseline (speedup 1.0000x reference)
#include <cuda_runtime.h>
#include <cuda_bf16.h>
#include <cuda_fp16.h>
#include <math.h>
#include <stdint.h>

#define B_  2
#define L_  2048
#define D_  2048
#define H_  16
#define DH_ 128
#define M_  (B_ * L_)   // 4096
#define C_  32          // chunk length
#define NC_ (L_ / C_)   // 64 chunks per (b,h)
#define NCH_ (B_ * H_ * NC_)  // 2048 chunk-heads

// ================= scratch (device globals; no allocations) =================
__device__ float g_q[M_ * D_];
__device__ float g_k[M_ * D_];
__device__ float g_v[M_ * D_];
__device__ float g_o[M_ * D_];
__device__ float g_beta[M_ * H_];
__device__ float g_ss[8 * M_ * H_];      // partial sumsq per (dv-quarter, dv-half)
__device__ __half g_Ahi[M_ * D_];        // fp16 A operand (X, then normalized o)
__device__ __half g_Wt[4 * D_ * D_];     // transposed weights [N,K] fp16, order q,k,v,o
// chunked delta-rule precompute (bf16 3-combo)
__device__ float g_W0[NCH_ * C_ * DH_];
__device__ __nv_bfloat16 g_TKh[NCH_ * C_ * DH_];
__device__ __nv_bfloat16 g_TKl[NCH_ * C_ * DH_];
__device__ __nv_bfloat16 g_Qch[NCH_ * C_ * DH_];
__device__ __nv_bfloat16 g_Qcl[NCH_ * C_ * DH_];
__device__ __nv_bfloat16 g_KTh[NCH_ * DH_ * C_];
__device__ __nv_bfloat16 g_KTl[NCH_ * DH_ * C_];
__device__ __nv_bfloat16 g_Ph[NCH_ * C_ * C_];
__device__ __nv_bfloat16 g_Pl[NCH_ * C_ * C_];

// ================= helpers =================
__device__ __forceinline__ uint32_t smem_u32(const void* p) {
    uint32_t a;
    asm("{ .reg .u64 t; cvta.to.shared.u64 t, %1; cvt.u32.u64 %0, t; }" : "=r"(a) : "l"(p));
    return a;
}
__device__ __forceinline__ void cp16(uint32_t dst, const void* src) {
    asm volatile("cp.async.cg.shared.global [%0], [%1], 16;" :: "r"(dst), "l"(src));
}
#define CP_COMMIT() asm volatile("cp.async.commit_group;" ::: "memory")
#define CP_WAIT(n)  asm volatile("cp.async.wait_group %0;" :: "n"(n) : "memory")

#define LDSM_X4(r0, r1, r2, r3, addr)                                            \
    asm volatile("ldmatrix.sync.aligned.m8n8.x4.shared.b16 {%0,%1,%2,%3}, [%4];" \
        : "=r"(r0), "=r"(r1), "=r"(r2), "=r"(r3) : "r"(addr))
#define LDSM_X2(r0, r1, addr)                                                    \
    asm volatile("ldmatrix.sync.aligned.m8n8.x2.shared.b16 {%0,%1}, [%2];"       \
        : "=r"(r0), "=r"(r1) : "r"(addr))

__device__ __forceinline__ void mma_bf16(float* d, const uint32_t* a, const uint32_t* b) {
    asm volatile(
        "mma.sync.aligned.m16n8k16.row.col.f32.bf16.bf16.f32 "
        "{%0,%1,%2,%3}, {%4,%5,%6,%7}, {%8,%9}, {%0,%1,%2,%3};"
        : "+f"(d[0]), "+f"(d[1]), "+f"(d[2]), "+f"(d[3])
        : "r"(a[0]), "r"(a[1]), "r"(a[2]), "r"(a[3]), "r"(b[0]), "r"(b[1]));
}
__device__ __forceinline__ void mma_f16(float* d, const uint32_t* a, const uint32_t* b) {
    asm volatile(
        "mma.sync.aligned.m16n8k16.row.col.f32.f16.f16.f32 "
        "{%0,%1,%2,%3}, {%4,%5,%6,%7}, {%8,%9}, {%0,%1,%2,%3};"
        : "+f"(d[0]), "+f"(d[1]), "+f"(d[2]), "+f"(d[3])
        : "r"(a[0]), "r"(a[1]), "r"(a[2]), "r"(a[3]), "r"(b[0]), "r"(b[1]));
}
__device__ __forceinline__ uint32_t pack_split(float v0, float v1, uint32_t& lo) {
    __nv_bfloat16 h0 = __float2bfloat16(v0), h1 = __float2bfloat16(v1);
    __nv_bfloat16 l0 = __float2bfloat16(v0 - __bfloat162float(h0));
    __nv_bfloat16 l1 = __float2bfloat16(v1 - __bfloat162float(h1));
    lo = ((uint32_t)__bfloat16_as_ushort(l1) << 16) | __bfloat16_as_ushort(l0);
    return ((uint32_t)__bfloat16_as_ushort(h1) << 16) | __bfloat16_as_ushort(h0);
}

// ================= fp32 -> fp16 =================
__global__ void __launch_bounds__(256) split_rows(const float4* __restrict__ X,
                                                  uint2* __restrict__ hi) {
    int i = blockIdx.x * 256 + threadIdx.x;
    float4 x = X[i];
    __half h0 = __float2half_rn(x.x), h1 = __float2half_rn(x.y);
    __half h2 = __float2half_rn(x.z), h3 = __float2half_rn(x.w);
    uint2 hv;
    hv.x = ((uint32_t)__half_as_ushort(h1) << 16) | __half_as_ushort(h0);
    hv.y = ((uint32_t)__half_as_ushort(h3) << 16) | __half_as_ushort(h2);
    hi[i] = hv;
}

// fp16 convert + deferred RMSNorm scale for o
__global__ void __launch_bounds__(256) split_rows_norm(const float4* __restrict__ X,
                                                       uint2* __restrict__ hi,
                                                       const float* __restrict__ ss) {
    int i = blockIdx.x * 256 + threadIdx.x;
    int m = i >> 9;
    int h = (i & 511) >> 5;
    size_t idx = (size_t)m * H_ + h;
    float s = 0.f;
#pragma unroll
    for (int p = 0; p < 8; p++) s += ss[(size_t)p * (M_ * H_) + idx];
    float r = rsqrtf(s * (1.0f / 128.0f) + 1e-5f);
    float4 x = X[i];
    x.x *= r; x.y *= r; x.z *= r; x.w *= r;
    __half h0 = __float2half_rn(x.x), h1 = __float2half_rn(x.y);
    __half h2 = __float2half_rn(x.z), h3 = __float2half_rn(x.w);
    uint2 hv;
    hv.x = ((uint32_t)__half_as_ushort(h1) << 16) | __half_as_ushort(h0);
    hv.y = ((uint32_t)__half_as_ushort(h3) << 16) | __half_as_ushort(h2);
    hi[i] = hv;
}

// transpose weights: W[k][n] fp32 -> Wt[n][k] fp16 (grid.z selects matrix)
__global__ void __launch_bounds__(256) split_transpose(
    const float* __restrict__ W0, const float* __restrict__ W1,
    const float* __restrict__ W2, const float* __restrict__ W3,
    __half* __restrict__ wt) {
    __shared__ float t[32][33];
    const float* W = (blockIdx.z == 0) ? W0 : (blockIdx.z == 1) ? W1
                   : (blockIdx.z == 2) ? W2 : W3;
    __half* ho = wt + (size_t)blockIdx.z * D_ * D_;
    const int n = blockIdx.x * 32 + threadIdx.x;
    const int k0 = blockIdx.y * 32;
#pragma unroll
    for (int i = threadIdx.y; i < 32; i += 8)
        t[i][threadIdx.x] = W[(size_t)(k0 + i) * D_ + n];
    __syncthreads();
#pragma unroll
    for (int i = threadIdx.y; i < 32; i += 8) {
        const int nn = blockIdx.x * 32 + i;
        ho[(size_t)nn * D_ + k0 + threadIdx.x] = __float2half_rn(t[threadIdx.x][i]);
    }
}

// ====== fp16 GEMM: BK=64, 3-stage, 2 CTAs/SM ================================
#define BM 128
#define BN 128
#define BK 64
#define LDSB 144                      // row stride bytes (128B + 16 pad)
#define TILE_B (128 * LDSB)           // 18432
#define STAGE_B (2 * TILE_B)          // 36864
#define NSTAGE 3
#define SMEM_DYN (NSTAGE * STAGE_B)   // 110592
#define NCHUNK (D_ / BK)              // 32

struct GemmArgs {
    const __half* Bw[3];
    float* C[3];
    int mode[3];
};

__device__ __forceinline__ void load_chunk(uint32_t sbase, int stage,
    const __half* Ahi, const __half* Bw,
    int m0, int n0, int kc, int tid) {
    const int r  = tid >> 1;
    const int c0 = (tid & 1) * 4;
    const uint32_t st = sbase + stage * STAGE_B;
    const size_t koff = (size_t)kc * BK;
    const __half* srcs[2] = {
        Ahi + (size_t)(m0 + r) * D_ + koff,
        Bw  + (size_t)(n0 + r) * D_ + koff };
#pragma unroll
    for (int t = 0; t < 2; t++) {
        uint32_t rowb = st + t * TILE_B + r * LDSB;
#pragma unroll
        for (int q = 0; q < 4; q++)
            cp16(rowb + (c0 + q) * 16, srcs[t] + (c0 + q) * 8);
    }
    CP_COMMIT();
}

__global__ void __launch_bounds__(256, 2) gemm_f16(
    const __half* __restrict__ Ahi, GemmArgs args) {
    extern __shared__ char smem_raw[];
    const int z = blockIdx.z;
    const __half* Bw = args.Bw[z];
    float* C = args.C[z];
    const int mode = args.mode[z];

    const int m0 = blockIdx.y * BM;
    const int n0 = blockIdx.x * BN;
    const int tid = threadIdx.x;
    const int wid = tid >> 5;
    const int lane = tid & 31;
    const int wm = (wid & 1) * 64;
    const int wn = (wid >> 1) * 32;
    const uint32_t sbase = smem_u32(smem_raw);

    const uint32_t a_row  = wm + (lane & 15);
    const uint32_t a_colb = ((lane >> 4) << 4);
    const uint32_t b_row  = wn + (lane & 7);
    const uint32_t b_colb = (((lane >> 3) & 1) << 4);

    float acc[4][4][4];
#pragma unroll
    for (int mi = 0; mi < 4; mi++)
#pragma unroll
        for (int ni = 0; ni < 4; ni++)
#pragma unroll
            for (int t = 0; t < 4; t++) acc[mi][ni][t] = 0.f;

    load_chunk(sbase, 0, Ahi, Bw, m0, n0, 0, tid);
    load_chunk(sbase, 1, Ahi, Bw, m0, n0, 1, tid);

    for (int c = 0; c < NCHUNK; c++) {
        CP_WAIT(1);
        __syncthreads();
        if (c + 2 < NCHUNK) {
            int s = (c + 2) % NSTAGE;
            load_chunk(sbase, s, Ahi, Bw, m0, n0, c + 2, tid);
        } else {
            CP_COMMIT();
        }

        const uint32_t st = sbase + (c % NSTAGE) * STAGE_B;
        const uint32_t tA = st;
        const uint32_t tB = st + TILE_B;

#pragma unroll
        for (int ks = 0; ks < 4; ks++) {
            const uint32_t kb = ks * 32;
            uint32_t ah[4][4], bf[4][2];
#pragma unroll
            for (int mi = 0; mi < 4; mi++) {
                uint32_t off = (a_row + mi * 16) * LDSB + a_colb + kb;
                LDSM_X4(ah[mi][0], ah[mi][1], ah[mi][2], ah[mi][3], tA + off);
            }
#pragma unroll
            for (int ni = 0; ni < 4; ni++) {
                uint32_t off = (b_row + ni * 8) * LDSB + b_colb + kb;
                LDSM_X2(bf[ni][0], bf[ni][1], tB + off);
            }
#pragma unroll
            for (int mi = 0; mi < 4; mi++)
#pragma unroll
                for (int ni = 0; ni < 4; ni++)
                    mma_f16(acc[mi][ni], ah[mi], bf[ni]);
        }
    }

    const int orow = m0 + wm + (lane >> 2);
    const int ocol = n0 + wn + 2 * (lane & 3);
#pragma unroll
    for (int mi = 0; mi < 4; mi++)
#pragma unroll
        for (int ni = 0; ni < 4; ni++) {
            float v0 = acc[mi][ni][0], v1 = acc[mi][ni][1];
            float v2 = acc[mi][ni][2], v3 = acc[mi][ni][3];
            if (mode == 1) {
                v0 = v0 / (1.f + expf(-v0));
                v1 = v1 / (1.f + expf(-v1));
                v2 = v2 / (1.f + expf(-v2));
                v3 = v3 / (1.f + expf(-v3));
            }
            float* p0 = C + (size_t)(orow + mi * 16) * D_ + ocol + ni * 8;
            float* p1 = C + (size_t)(orow + mi * 16 + 8) * D_ + ocol + ni * 8;
            *(float2*)p0 = make_float2(v0, v1);
            *(float2*)p1 = make_float2(v2, v3);
        }
}

// ========== beta projection: cp.async double-buffered tiled GEMM ===========
__global__ void __launch_bounds__(256) beta_gemm(const float* __restrict__ X,
                                                 const float* __restrict__ Wb,
                                                 float* __restrict__ beta) {
    __shared__ float Xs[2][16][132];
    __shared__ float Ws[2][128][16];
    const int m0 = blockIdx.x * 16;
    const int tid = threadIdx.x;
    const int row = tid >> 4, n = tid & 15;
    const uint32_t xb = smem_u32(&Xs[0][0][0]);
    const uint32_t wb = smem_u32(&Ws[0][0][0]);

    auto load_tile = [&](int buf, int kt) {
        const uint32_t xs = xb + buf * (16 * 132 * 4);
        const uint32_t ws = wb + buf * (128 * 16 * 4);
#pragma unroll
        for (int i = tid; i < 512; i += 256) {
            int r = i >> 5, c16 = i & 31;
            cp16(xs + r * 528 + c16 * 16, X + (size_t)(m0 + r) * D_ + kt + c16 * 4);
        }
#pragma unroll
        for (int i = tid; i < 512; i += 256) {
            int r = i >> 2, cc = i & 3;
            cp16(ws + r * 64 + cc * 16, Wb + (size_t)(kt + r) * H_ + cc * 4);
        }
        CP_COMMIT();
    };

    float acc = 0.f;
    load_tile(0, 0);
    for (int t = 0; t < 16; t++) {
        if (t + 1 < 16) load_tile((t + 1) & 1, (t + 1) * 128);
        else            CP_COMMIT();
        CP_WAIT(1);
        __syncthreads();
        const int buf = t & 1;
#pragma unroll 16
        for (int k = 0; k < 128; k++) acc += Xs[buf][row][k] * Ws[buf][k][n];
        __syncthreads();
    }
    beta[(size_t)(m0 + row) * H_ + n] = 1.f / (1.f + expf(-acc));
}

// ================= PRE: l2norm fused + per-chunk WY precompute ==============
// (R13 barrier-based substitution — compact code, no I$ thrash)
__global__ void __launch_bounds__(128) pre_chunk(
    const float* __restrict__ q, const float* __restrict__ k,
    const float* __restrict__ v, const float* __restrict__ beta,
    float* __restrict__ W0g,
    __nv_bfloat16* __restrict__ TKh, __nv_bfloat16* __restrict__ TKl,
    __nv_bfloat16* __restrict__ Qh,  __nv_bfloat16* __restrict__ Ql,
    __nv_bfloat16* __restrict__ KTh, __nv_bfloat16* __restrict__ KTl,
    __nv_bfloat16* __restrict__ Ph,  __nv_bfloat16* __restrict__ Pl) {
    extern __shared__ float sm[];
    float* Kc  = sm;               // [32][128]
    float* Qc  = Kc + 32 * 128;    // [32][128]
    float* X   = Qc + 32 * 128;    // [32][256]  [bV | bK]
    float* Asm = X + 32 * 256;     // [32][32]
    float* bsm = Asm + 32 * 32;    // [32]

    const int ch = blockIdx.x;
    const int c  = ch & (NC_ - 1);
    const int bh = ch >> 6;
    const int b  = bh >> 4;
    const int h  = bh & 15;
    const int t0 = c * C_;
    const int tid = threadIdx.x;
    const size_t base0 = (size_t)b * L_ * D_ + (size_t)h * DH_;

    if (tid < 32) bsm[tid] = beta[((size_t)b * L_ + t0 + tid) * H_ + h];
    for (int i = tid; i < 32 * 32; i += 128) {
        int r = i >> 5, c4 = (i & 31) * 4;
        const size_t g = base0 + (size_t)(t0 + r) * D_ + c4;
        *(float4*)(Kc + r * 128 + c4) = *(const float4*)(k + g);
        *(float4*)(Qc + r * 128 + c4) = *(const float4*)(q + g);
        *(float4*)(X + r * 256 + c4)  = *(const float4*)(v + g);
    }
    __syncthreads();

    {
        const int w = tid >> 5, lane = tid & 31;
#pragma unroll
        for (int r = w * 8; r < w * 8 + 8; r++) {
            float4 kv = *(float4*)(Kc + r * 128 + lane * 4);
            float4 qv = *(float4*)(Qc + r * 128 + lane * 4);
            float sk = kv.x * kv.x + kv.y * kv.y + kv.z * kv.z + kv.w * kv.w;
            float sq = qv.x * qv.x + qv.y * qv.y + qv.z * qv.z + qv.w * qv.w;
#pragma unroll
            for (int off = 16; off; off >>= 1) {
                sk += __shfl_xor_sync(0xffffffffu, sk, off);
                sq += __shfl_xor_sync(0xffffffffu, sq, off);
            }
            float ik = 1.0f / fmaxf(sqrtf(sk), 1e-12f);
            float iq = 0.08838834764831845f / fmaxf(sqrtf(sq), 1e-12f);
            kv.x *= ik; kv.y *= ik; kv.z *= ik; kv.w *= ik;
            qv.x *= iq; qv.y *= iq; qv.z *= iq; qv.w *= iq;
            *(float4*)(Kc + r * 128 + lane * 4) = kv;
            *(float4*)(Qc + r * 128 + lane * 4) = qv;
        }
    }
    __syncthreads();

    for (int i = tid; i < 32 * 32; i += 128) {
        int r = i >> 5, c4 = (i & 31) * 4;
        float bt = bsm[r];
        float4 kv = *(float4*)(Kc + r * 128 + c4);
        kv.x *= bt; kv.y *= bt; kv.z *= bt; kv.w *= bt;
        *(float4*)(X + r * 256 + 128 + c4) = kv;
        float4 vv = *(float4*)(X + r * 256 + c4);
        vv.x *= bt; vv.y *= bt; vv.z *= bt; vv.w *= bt;
        *(float4*)(X + r * 256 + c4) = vv;
    }

    const int i_ = tid >> 2, j0 = (tid & 3) * 8;
    float accA[8], accP[8];
#pragma unroll
    for (int e = 0; e < 8; e++) { accA[e] = 0.f; accP[e] = 0.f; }
    for (int d4 = 0; d4 < 128; d4 += 4) {
        float4 ki = *(const float4*)(Kc + i_ * 128 + d4);
        float4 qi = *(const float4*)(Qc + i_ * 128 + d4);
#pragma unroll
        for (int e = 0; e < 8; e++) {
            float4 kj = *(const float4*)(Kc + (j0 + e) * 128 + d4);
            accA[e] += ki.x * kj.x + ki.y * kj.y + ki.z * kj.z + ki.w * kj.w;
            accP[e] += qi.x * kj.x + qi.y * kj.y + qi.z * kj.z + qi.w * kj.w;
        }
    }
    const float bi = bsm[i_];
#pragma unroll
    for (int e = 0; e < 8; e++) {
        int j = j0 + e;
        Asm[i_ * 32 + j] = (j < i_) ? bi * accA[e] : 0.f;
        float pv = (j <= i_) ? accP[e] : 0.f;
        __nv_bfloat16 phv = __float2bfloat16(pv);
        Ph[(size_t)ch * 1024 + i_ * 32 + j] = phv;
        Pl[(size_t)ch * 1024 + i_ * 32 + j] = __float2bfloat16(pv - __bfloat162float(phv));
    }
    __syncthreads();

    for (int i = 1; i < 32; i++) {
        float f0 = 0.f, f1 = 0.f;
        for (int j = 0; j < i; j++) {
            float a = Asm[i * 32 + j];
            f0 += a * X[j * 256 + tid];
            f1 += a * X[j * 256 + 128 + tid];
        }
        X[i * 256 + tid]       -= f0;
        X[i * 256 + 128 + tid] -= f1;
        __syncthreads();
    }

    for (int i = tid; i < 32 * 128; i += 128) {
        int n = i >> 7, m = i & 127;
        W0g[(size_t)ch * 4096 + i] = X[n * 256 + m];
        float tkv = X[n * 256 + 128 + m];
        __nv_bfloat16 th_ = __float2bfloat16(tkv);
        TKh[(size_t)ch * 4096 + i] = th_;
        TKl[(size_t)ch * 4096 + i] = __float2bfloat16(tkv - __bfloat162float(th_));
        float qv = Qc[n * 128 + m];
        __nv_bfloat16 qh_ = __float2bfloat16(qv);
        Qh[(size_t)ch * 4096 + i] = qh_;
        Ql[(size_t)ch * 4096 + i] = __float2bfloat16(qv - __bfloat162float(qh_));
    }
#pragma unroll
    for (int n = 0; n < 32; n++) {
        float kv = Kc[n * 128 + tid];
        __nv_bfloat16 kh_ = __float2bfloat16(kv);
        KTh[(size_t)ch * 4096 + tid * 32 + n] = kh_;
        KTl[(size_t)ch * 4096 + tid * 32 + n] = __float2bfloat16(kv - __bfloat162float(kh_));
    }
}

// ====== SEQ: dv-split x4 (4 CTAs per (b,h)), cp.async operand prefetch ======
#define SST 272
#define WST 80
#define OS_SHI 0
#define OS_SLO 8704
#define OS_WTH 17408
#define OS_WTL 19968
#define OS_OPS 22784
#define OB_TKH 0
#define OB_TKL 8704
#define OB_QH  17408
#define OB_QL  26112
#define OB_KTH 34816
#define OB_KTL 45056
#define OB_PH  55296
#define OB_PL  57856
#define OB_W0  60416
#define OB_SIZE 64512
#define SEQ_SMEM (OS_OPS + 2 * OB_SIZE)

__device__ __forceinline__ void seq_load_ops(uint32_t ob, size_t ch, int dvq, int tid,
    const float* W0g,
    const __nv_bfloat16* TKh, const __nv_bfloat16* TKl,
    const __nv_bfloat16* Qh,  const __nv_bfloat16* Ql,
    const __nv_bfloat16* KTh, const __nv_bfloat16* KTl,
    const __nv_bfloat16* Ph,  const __nv_bfloat16* Pl) {
    for (int i = tid; i < 512; i += 256) {
        int r = i >> 4, q = i & 15;
        size_t g = ch * 4096 + (size_t)r * 128 + q * 8;
        cp16(ob + OB_TKH + r * SST + q * 16, TKh + g);
        cp16(ob + OB_TKL + r * SST + q * 16, TKl + g);
        cp16(ob + OB_QH  + r * SST + q * 16, Qh + g);
        cp16(ob + OB_QL  + r * SST + q * 16, Ql + g);
    }
    for (int i = tid; i < 512; i += 256) {
        int r = i >> 2, q = i & 3;
        size_t g = ch * 4096 + (size_t)r * 32 + q * 8;
        cp16(ob + OB_KTH + r * WST + q * 16, KTh + g);
        cp16(ob + OB_KTL + r * WST + q * 16, KTl + g);
    }
    if (tid < 128) {
        int r = tid >> 2, q = tid & 3;
        size_t g = ch * 1024 + (size_t)r * 32 + q * 8;
        cp16(ob + OB_PH + r * WST + q * 16, Ph + g);
        cp16(ob + OB_PL + r * WST + q * 16, Pl + g);
    }
    {
        int r = tid >> 3, q = tid & 7;
        cp16(ob + OB_W0 + r * 128 + q * 16,
             W0g + ch * 4096 + (size_t)r * 128 + dvq * 32 + q * 4);
    }
    CP_COMMIT();
}

__global__ void __launch_bounds__(256, 1) seq_chunk(
    const float* __restrict__ W0g,
    const __nv_bfloat16* __restrict__ TKh, const __nv_bfloat16* __restrict__ TKl,
    const __nv_bfloat16* __restrict__ Qh,  const __nv_bfloat16* __restrict__ Ql,
    const __nv_bfloat16* __restrict__ KTh, const __nv_bfloat16* __restrict__ KTl,
    const __nv_bfloat16* __restrict__ Ph,  const __nv_bfloat16* __restrict__ Pl,
    const float* __restrict__ wnorm, float* __restrict__ o,
    float* __restrict__ oss) {
    extern __shared__ char smraw[];
    const int bh  = blockIdx.x >> 2;
    const int dvq = blockIdx.x & 3;
    const int b = bh >> 4, h = bh & 15;
    const int tid = threadIdx.x, wid = tid >> 5, lane = tid & 31;
    const uint32_t sb = smem_u32(smraw);

    seq_load_ops(sb + OS_OPS, (size_t)bh * NC_, dvq, tid,
                 W0g, TKh, TKl, Qh, Ql, KTh, KTl, Ph, Pl);
    for (int i = tid; i < OS_OPS / 16; i += 256)
        ((uint4*)smraw)[i] = make_uint4(0, 0, 0, 0);

    float Sfr[4][4];
#pragma unroll
    for (int ni = 0; ni < 4; ni++)
#pragma unroll
        for (int e = 0; e < 4; e++) Sfr[ni][e] = 0.f;

    const int wm   = (wid & 1) * 16;
    const int tg   = wid >> 1;
    const int wn8  = tg * 8;
    const int wn32 = tg * 32;
    const int a_r = lane & 15, a_cB = (lane >> 4) << 4;
    const int b_r = lane & 7,  b_cB = ((lane >> 3) & 1) << 4;
    const int fr = lane >> 2, fc = (lane & 3) * 2;
    const int ssl = dvq * 2 + (wid & 1);   // oss slice 0..7

    float wnr[2];
#pragma unroll
    for (int pp = 0; pp < 2; pp++)
        wnr[pp] = wnorm[dvq * 32 + wm + pp * 8 + fr];

    for (int c = 0; c < NC_; c++) {
        const size_t ch = (size_t)bh * NC_ + c;
        const int cb = c & 1;
        const uint32_t ob = sb + OS_OPS + cb * OB_SIZE;
        float* W0s = (float*)(smraw + OS_OPS + cb * OB_SIZE + OB_W0);

        __syncthreads();
        if (c + 1 < NC_)
            seq_load_ops(sb + OS_OPS + (1 - cb) * OB_SIZE, ch + 1, dvq, tid,
                         W0g, TKh, TKl, Qh, Ql, KTh, KTl, Ph, Pl);
        else
            CP_COMMIT();
        CP_WAIT(1);
        __syncthreads();

        // step 1: Wt = W0^T - Ssm @ TK^T
        float acc[4];
#pragma unroll
        for (int e = 0; e < 4; e++) acc[e] = 0.f;
#pragma unroll
        for (int ks = 0; ks < 8; ks++) {
            uint32_t ah[4], al[4], bhf[2], blf[2];
            uint32_t offa = (wm + a_r) * SST + a_cB + ks * 32;
            LDSM_X4(ah[0], ah[1], ah[2], ah[3], sb + OS_SHI + offa);
            LDSM_X4(al[0], al[1], al[2], al[3], sb + OS_SLO + offa);
            uint32_t offb = (wn8 + b_r) * SST + b_cB + ks * 32;
            LDSM_X2(bhf[0], bhf[1], ob + OB_TKH + offb);
            LDSM_X2(blf[0], blf[1], ob + OB_TKL + offb);
            mma_bf16(acc, ah, bhf);
            mma_bf16(acc, ah, blf);
            mma_bf16(acc, al, bhf);
        }
#pragma unroll
        for (int pp = 0; pp < 2; pp++) {
            int m = wm + fr + pp * 8;
            int n0 = wn8 + fc;
            float v0 = W0s[n0 * 32 + m] - acc[pp * 2 + 0];
            float v1 = W0s[(n0 + 1) * 32 + m] - acc[pp * 2 + 1];
            uint32_t lo, hi = pack_split(v0, v1, lo);
            *(uint32_t*)(smraw + OS_WTH + m * WST + n0 * 2) = hi;
            *(uint32_t*)(smraw + OS_WTL + m * WST + n0 * 2) = lo;
        }
        __syncthreads();

        // step 2: Ot = Ssm @ Q^T + Wt @ P^T
        float oacc[4];
#pragma unroll
        for (int e = 0; e < 4; e++) oacc[e] = 0.f;
#pragma unroll
        for (int ks = 0; ks < 8; ks++) {
            uint32_t ah[4], al[4], bhf[2], blf[2];
            uint32_t offa = (wm + a_r) * SST + a_cB + ks * 32;
            LDSM_X4(ah[0], ah[1], ah[2], ah[3], sb + OS_SHI + offa);
            LDSM_X4(al[0], al[1], al[2], al[3], sb + OS_SLO + offa);
            uint32_t offb = (wn8 + b_r) * SST + b_cB + ks * 32;
            LDSM_X2(bhf[0], bhf[1], ob + OB_QH + offb);
            LDSM_X2(blf[0], blf[1], ob + OB_QL + offb);
            mma_bf16(oacc, ah, bhf);
            mma_bf16(oacc, ah, blf);
            mma_bf16(oacc, al, bhf);
        }
#pragma unroll
        for (int ks = 0; ks < 2; ks++) {
            uint32_t ah[4], al[4], bhf[2], blf[2];
            uint32_t offa = (wm + a_r) * WST + a_cB + ks * 32;
            LDSM_X4(ah[0], ah[1], ah[2], ah[3], sb + OS_WTH + offa);
            LDSM_X4(al[0], al[1], al[2], al[3], sb + OS_WTL + offa);
            uint32_t offb = (wn8 + b_r) * WST + b_cB + ks * 32;
            LDSM_X2(bhf[0], bhf[1], ob + OB_PH + offb);
            LDSM_X2(blf[0], blf[1], ob + OB_PL + offb);
            mma_bf16(oacc, ah, bhf);
            mma_bf16(oacc, ah, blf);
            mma_bf16(oacc, al, bhf);
        }
        // per-warp partial sumsq -> direct oss store (no atomics)
        {
            float s0 = oacc[0] * oacc[0] + oacc[2] * oacc[2];
            float s1 = oacc[1] * oacc[1] + oacc[3] * oacc[3];
#pragma unroll
            for (int off = 4; off <= 16; off <<= 1) {
                s0 += __shfl_xor_sync(0xffffffffu, s0, off);
                s1 += __shfl_xor_sync(0xffffffffu, s1, off);
            }
            if (lane < 4) {
                size_t tokbase = ((size_t)b * L_ + c * C_ + wn8 + 2 * lane) * H_ + h;
                oss[(size_t)ssl * (M_ * H_) + tokbase]      = s0;
                oss[(size_t)ssl * (M_ * H_) + tokbase + H_] = s1;
            }
        }

        // store o (unnormalized * wn)
        {
            const size_t obase = (size_t)b * L_ * D_ + (size_t)h * DH_ + (size_t)(c * C_) * D_
                               + dvq * 32;
            int n0 = wn8 + fc;
#pragma unroll
            for (int pp = 0; pp < 2; pp++) {
                int m = wm + fr + pp * 8;
                o[obase + (size_t)n0 * D_ + m] = oacc[pp * 2] * wnr[pp];
                o[obase + (size_t)(n0 + 1) * D_ + m] = oacc[pp * 2 + 1] * wnr[pp];
            }
        }
        __syncthreads();   // step-2 S reads complete before step-3 S writes

        // step 3: Ssm += Wt @ K
#pragma unroll
        for (int ks = 0; ks < 2; ks++) {
            uint32_t ah[4], al[4];
            uint32_t offa = (wm + a_r) * WST + a_cB + ks * 32;
            LDSM_X4(ah[0], ah[1], ah[2], ah[3], sb + OS_WTH + offa);
            LDSM_X4(al[0], al[1], al[2], al[3], sb + OS_WTL + offa);
#pragma unroll
            for (int ni = 0; ni < 4; ni++) {
                uint32_t bhf[2], blf[2];
                uint32_t offb = (wn32 + ni * 8 + b_r) * WST + b_cB + ks * 32;
                LDSM_X2(bhf[0], bhf[1], ob + OB_KTH + offb);
                LDSM_X2(blf[0], blf[1], ob + OB_KTL + offb);
                mma_bf16(Sfr[ni], ah, bhf);
                mma_bf16(Sfr[ni], ah, blf);
                mma_bf16(Sfr[ni], al, bhf);
            }
        }
#pragma unroll
        for (int ni = 0; ni < 4; ni++)
#pragma unroll
            for (int pp = 0; pp < 2; pp++) {
                int m = wm + fr + pp * 8;
                int n0 = wn32 + ni * 8 + fc;
                uint32_t lo, hi = pack_split(Sfr[ni][pp * 2], Sfr[ni][pp * 2 + 1], lo);
                *(uint32_t*)(smraw + OS_SHI + m * SST + n0 * 2) = hi;
                *(uint32_t*)(smraw + OS_SLO + m * SST + n0 * 2) = lo;
            }
    }
}

// ================= launch =================
extern "C" void kernel_launch(void* const* d_in, const int* in_sizes, int n_in,
                              void* d_out, int out_size) {
    const float* X  = (const float*)d_in[0];
    const float* Wq = (const float*)d_in[1];
    const float* Wk = (const float*)d_in[2];
    const float* Wv = (const float*)d_in[3];
    const float* Wb = (const float*)d_in[4];
    const float* wn = (const float*)d_in[5];
    const float* Wo = (const float*)d_in[6];
    float* out = (float*)d_out;

    float *gq, *gk, *gv, *go, *gb, *gW0, *gss;
    __half *ahi, *wt;
    __nv_bfloat16 *tkh, *tkl, *qch, *qcl, *kth, *ktl, *ph, *pl;
    cudaGetSymbolAddress((void**)&gq, g_q);
    cudaGetSymbolAddress((void**)&gk, g_k);
    cudaGetSymbolAddress((void**)&gv, g_v);
    cudaGetSymbolAddress((void**)&go, g_o);
    cudaGetSymbolAddress((void**)&gb, g_beta);
    cudaGetSymbolAddress((void**)&gss, g_ss);
    cudaGetSymbolAddress((void**)&ahi, g_Ahi);
    cudaGetSymbolAddress((void**)&wt, g_Wt);
    cudaGetSymbolAddress((void**)&gW0, g_W0);
    cudaGetSymbolAddress((void**)&tkh, g_TKh);
    cudaGetSymbolAddress((void**)&tkl, g_TKl);
    cudaGetSymbolAddress((void**)&qch, g_Qch);
    cudaGetSymbolAddress((void**)&qcl, g_Qcl);
    cudaGetSymbolAddress((void**)&kth, g_KTh);
    cudaGetSymbolAddress((void**)&ktl, g_KTl);
    cudaGetSymbolAddress((void**)&ph, g_Ph);
    cudaGetSymbolAddress((void**)&pl, g_Pl);

    cudaFuncSetAttribute(gemm_f16, cudaFuncAttributeMaxDynamicSharedMemorySize, SMEM_DYN);
    cudaFuncSetAttribute(pre_chunk, cudaFuncAttributeMaxDynamicSharedMemorySize, 69760);
    cudaFuncSetAttribute(seq_chunk, cudaFuncAttributeMaxDynamicSharedMemorySize, SEQ_SMEM);

    const int NSPLIT = M_ * D_ / 4 / 256;

    split_rows<<<NSPLIT, 256>>>((const float4*)X, (uint2*)ahi);
    split_transpose<<<dim3(D_ / 32, D_ / 32, 4), dim3(32, 8)>>>(Wq, Wk, Wv, Wo, wt);

    GemmArgs qa;
    qa.Bw[0] = wt;
    qa.Bw[1] = wt + (size_t)D_ * D_;
    qa.Bw[2] = wt + (size_t)2 * D_ * D_;
    qa.C[0] = gq; qa.C[1] = gk; qa.C[2] = gv;
    qa.mode[0] = 0; qa.mode[1] = 0; qa.mode[2] = 1;
    gemm_f16<<<dim3(D_ / BN, M_ / BM, 3), 256, SMEM_DYN>>>(ahi, qa);

    beta_gemm<<<M_ / 16, 256>>>(X, Wb, gb);

    pre_chunk<<<NCH_, 128, 69760>>>(gq, gk, gv, gb, gW0, tkh, tkl, qch, qcl, kth, ktl, ph, pl);
    seq_chunk<<<4 * B_ * H_, 256, SEQ_SMEM>>>(gW0, tkh, tkl, qch, qcl, kth, ktl, ph, pl, wn, go, gss);

    split_rows_norm<<<NSPLIT, 256>>>((const float4*)go, (uint2*)ahi, gss);
    GemmArgs oa;
    oa.Bw[0] = wt + (size_t)3 * D_ * D_;
    oa.Bw[1] = oa.Bw[0];
    oa.Bw[2] = oa.Bw[0];
    oa.C[0] = out; oa.C[1] = out; oa.C[2] = out;
    oa.mode[0] = 0; oa.mode[1] = 0; oa.mode[2] = 0;
    gemm_f16<<<dim3(D_ / BN, M_ / BM, 1), 256, SMEM_DYN>>>(ahi, oa);
}

// round 16
// speedup vs baseline: 1.0691x; 1.0691x over previous
#include <cuda_runtime.h>
#include <cuda_bf16.h>
#include <cuda_fp16.h>
#include <math.h>
#include <stdint.h>

#define B_  2
#define L_  2048
#define D_  2048
#define H_  16
#define DH_ 128
#define M_  (B_ * L_)   // 4096
#define C_  32          // chunk length
#define NC_ (L_ / C_)   // 64 chunks per (b,h)
#define NCH_ (B_ * H_ * NC_)  // 2048 chunk-heads

// ================= scratch (device globals; no allocations) =================
__device__ float g_q[M_ * D_];
__device__ float g_k[M_ * D_];
__device__ float g_v[M_ * D_];
__device__ float g_o[M_ * D_];
__device__ float g_beta[M_ * H_];
__device__ float g_ss[4 * M_ * H_];      // partial sumsq per dv-quarter
__device__ __half g_Ahi[M_ * D_];        // fp16 A operand (X, then normalized o)
__device__ __half g_Wt[4 * D_ * D_];     // transposed weights [N,K] fp16, order q,k,v,o
// chunked delta-rule precompute (bf16 3-combo)
__device__ float g_W0[NCH_ * C_ * DH_];
__device__ __nv_bfloat16 g_TKh[NCH_ * C_ * DH_];
__device__ __nv_bfloat16 g_TKl[NCH_ * C_ * DH_];
__device__ __nv_bfloat16 g_Qch[NCH_ * C_ * DH_];
__device__ __nv_bfloat16 g_Qcl[NCH_ * C_ * DH_];
__device__ __nv_bfloat16 g_KTh[NCH_ * DH_ * C_];
__device__ __nv_bfloat16 g_KTl[NCH_ * DH_ * C_];
__device__ __nv_bfloat16 g_Ph[NCH_ * C_ * C_];
__device__ __nv_bfloat16 g_Pl[NCH_ * C_ * C_];

// ================= helpers =================
__device__ __forceinline__ uint32_t smem_u32(const void* p) {
    uint32_t a;
    asm("{ .reg .u64 t; cvta.to.shared.u64 t, %1; cvt.u32.u64 %0, t; }" : "=r"(a) : "l"(p));
    return a;
}
__device__ __forceinline__ void cp16(uint32_t dst, const void* src) {
    asm volatile("cp.async.cg.shared.global [%0], [%1], 16;" :: "r"(dst), "l"(src));
}
#define CP_COMMIT() asm volatile("cp.async.commit_group;" ::: "memory")
#define CP_WAIT(n)  asm volatile("cp.async.wait_group %0;" :: "n"(n) : "memory")

#define LDSM_X4(r0, r1, r2, r3, addr)                                            \
    asm volatile("ldmatrix.sync.aligned.m8n8.x4.shared.b16 {%0,%1,%2,%3}, [%4];" \
        : "=r"(r0), "=r"(r1), "=r"(r2), "=r"(r3) : "r"(addr))
#define LDSM_X2(r0, r1, addr)                                                    \
    asm volatile("ldmatrix.sync.aligned.m8n8.x2.shared.b16 {%0,%1}, [%2];"       \
        : "=r"(r0), "=r"(r1) : "r"(addr))

__device__ __forceinline__ void mma_bf16(float* d, const uint32_t* a, const uint32_t* b) {
    asm volatile(
        "mma.sync.aligned.m16n8k16.row.col.f32.bf16.bf16.f32 "
        "{%0,%1,%2,%3}, {%4,%5,%6,%7}, {%8,%9}, {%0,%1,%2,%3};"
        : "+f"(d[0]), "+f"(d[1]), "+f"(d[2]), "+f"(d[3])
        : "r"(a[0]), "r"(a[1]), "r"(a[2]), "r"(a[3]), "r"(b[0]), "r"(b[1]));
}
__device__ __forceinline__ void mma_f16(float* d, const uint32_t* a, const uint32_t* b) {
    asm volatile(
        "mma.sync.aligned.m16n8k16.row.col.f32.f16.f16.f32 "
        "{%0,%1,%2,%3}, {%4,%5,%6,%7}, {%8,%9}, {%0,%1,%2,%3};"
        : "+f"(d[0]), "+f"(d[1]), "+f"(d[2]), "+f"(d[3])
        : "r"(a[0]), "r"(a[1]), "r"(a[2]), "r"(a[3]), "r"(b[0]), "r"(b[1]));
}
__device__ __forceinline__ uint32_t pack_split(float v0, float v1, uint32_t& lo) {
    __nv_bfloat16 h0 = __float2bfloat16(v0), h1 = __float2bfloat16(v1);
    __nv_bfloat16 l0 = __float2bfloat16(v0 - __bfloat162float(h0));
    __nv_bfloat16 l1 = __float2bfloat16(v1 - __bfloat162float(h1));
    lo = ((uint32_t)__bfloat16_as_ushort(l1) << 16) | __bfloat16_as_ushort(l0);
    return ((uint32_t)__bfloat16_as_ushort(h1) << 16) | __bfloat16_as_ushort(h0);
}

// ================= fp32 -> fp16 =================
__global__ void __launch_bounds__(256) split_rows(const float4* __restrict__ X,
                                                  uint2* __restrict__ hi) {
    int i = blockIdx.x * 256 + threadIdx.x;
    float4 x = X[i];
    __half h0 = __float2half_rn(x.x), h1 = __float2half_rn(x.y);
    __half h2 = __float2half_rn(x.z), h3 = __float2half_rn(x.w);
    uint2 hv;
    hv.x = ((uint32_t)__half_as_ushort(h1) << 16) | __half_as_ushort(h0);
    hv.y = ((uint32_t)__half_as_ushort(h3) << 16) | __half_as_ushort(h2);
    hi[i] = hv;
}

// fp16 convert + deferred RMSNorm scale for o
__global__ void __launch_bounds__(256) split_rows_norm(const float4* __restrict__ X,
                                                       uint2* __restrict__ hi,
                                                       const float* __restrict__ ss) {
    int i = blockIdx.x * 256 + threadIdx.x;
    int m = i >> 9;
    int h = (i & 511) >> 5;
    size_t idx = (size_t)m * H_ + h;
    float s = ss[idx] + ss[(size_t)M_ * H_ + idx]
            + ss[(size_t)2 * M_ * H_ + idx] + ss[(size_t)3 * M_ * H_ + idx];
    float r = rsqrtf(s * (1.0f / 128.0f) + 1e-5f);
    float4 x = X[i];
    x.x *= r; x.y *= r; x.z *= r; x.w *= r;
    __half h0 = __float2half_rn(x.x), h1 = __float2half_rn(x.y);
    __half h2 = __float2half_rn(x.z), h3 = __float2half_rn(x.w);
    uint2 hv;
    hv.x = ((uint32_t)__half_as_ushort(h1) << 16) | __half_as_ushort(h0);
    hv.y = ((uint32_t)__half_as_ushort(h3) << 16) | __half_as_ushort(h2);
    hi[i] = hv;
}

// transpose weights: W[k][n] fp32 -> Wt[n][k] fp16 (grid.z selects matrix)
__global__ void __launch_bounds__(256) split_transpose(
    const float* __restrict__ W0, const float* __restrict__ W1,
    const float* __restrict__ W2, const float* __restrict__ W3,
    __half* __restrict__ wt) {
    __shared__ float t[32][33];
    const float* W = (blockIdx.z == 0) ? W0 : (blockIdx.z == 1) ? W1
                   : (blockIdx.z == 2) ? W2 : W3;
    __half* ho = wt + (size_t)blockIdx.z * D_ * D_;
    const int n = blockIdx.x * 32 + threadIdx.x;
    const int k0 = blockIdx.y * 32;
#pragma unroll
    for (int i = threadIdx.y; i < 32; i += 8)
        t[i][threadIdx.x] = W[(size_t)(k0 + i) * D_ + n];
    __syncthreads();
#pragma unroll
    for (int i = threadIdx.y; i < 32; i += 8) {
        const int nn = blockIdx.x * 32 + i;
        ho[(size_t)nn * D_ + k0 + threadIdx.x] = __float2half_rn(t[threadIdx.x][i]);
    }
}

// ====== fp16 single-combo GEMM: R13 config (BK=32, 3-stage, 2 CTAs/SM) ======
#define BM 128
#define BN 128
#define BK 32
#define LDS_ 40
#define TILE_B (128 * LDS_ * 2)       // 10240
#define STAGE_B (2 * TILE_B)          // A, B = 20480
#define NSTAGE 3
#define SMEM_DYN (NSTAGE * STAGE_B)   // 61440
#define NCHUNK (D_ / BK)

struct GemmArgs {
    const __half* Bw[3];
    float* C[3];
    int mode[3];
};

__device__ __forceinline__ void load_chunk(uint32_t sbase, int stage,
    const __half* Ahi, const __half* Bw,
    int m0, int n0, int kc, int tid) {
    const int r  = tid >> 1;
    const int c0 = (tid & 1) * 2;
    const uint32_t st = sbase + stage * STAGE_B;
    const size_t koff = (size_t)kc * BK;
    const __half* srcs[2] = {
        Ahi + (size_t)(m0 + r) * D_ + koff,
        Bw  + (size_t)(n0 + r) * D_ + koff };
#pragma unroll
    for (int t = 0; t < 2; t++) {
        uint32_t rowb = st + t * TILE_B + r * (LDS_ * 2);
        cp16(rowb + (c0 + 0) * 16, srcs[t] + (c0 + 0) * 8);
        cp16(rowb + (c0 + 1) * 16, srcs[t] + (c0 + 1) * 8);
    }
    CP_COMMIT();
}

__global__ void __launch_bounds__(256, 2) gemm_f16(
    const __half* __restrict__ Ahi, GemmArgs args) {
    extern __shared__ char smem_raw[];
    const int z = blockIdx.z;
    const __half* Bw = args.Bw[z];
    float* C = args.C[z];
    const int mode = args.mode[z];

    const int m0 = blockIdx.y * BM;
    const int n0 = blockIdx.x * BN;
    const int tid = threadIdx.x;
    const int wid = tid >> 5;
    const int lane = tid & 31;
    const int wm = (wid & 1) * 64;
    const int wn = (wid >> 1) * 32;
    const uint32_t sbase = smem_u32(smem_raw);

    const uint32_t a_row  = wm + (lane & 15);
    const uint32_t a_colb = ((lane >> 4) << 4);
    const uint32_t b_row  = wn + (lane & 7);
    const uint32_t b_colb = (((lane >> 3) & 1) << 4);

    float acc[4][4][4];
#pragma unroll
    for (int mi = 0; mi < 4; mi++)
#pragma unroll
        for (int ni = 0; ni < 4; ni++)
#pragma unroll
            for (int t = 0; t < 4; t++) acc[mi][ni][t] = 0.f;

    load_chunk(sbase, 0, Ahi, Bw, m0, n0, 0, tid);
    load_chunk(sbase, 1, Ahi, Bw, m0, n0, 1, tid);

    for (int c = 0; c < NCHUNK; c++) {
        CP_WAIT(1);
        __syncthreads();
        if (c + 2 < NCHUNK) {
            int s = (c + 2) % NSTAGE;
            load_chunk(sbase, s, Ahi, Bw, m0, n0, c + 2, tid);
        } else {
            CP_COMMIT();
        }

        const uint32_t st  = sbase + (c % NSTAGE) * STAGE_B;
        const uint32_t tA  = st;
        const uint32_t tB  = st + TILE_B;

#pragma unroll
        for (int ks = 0; ks < 2; ks++) {
            const uint32_t kb = ks * 32;
            uint32_t ah[4][4], bf[4][2];
#pragma unroll
            for (int mi = 0; mi < 4; mi++) {
                uint32_t off = (a_row + mi * 16) * (LDS_ * 2) + a_colb + kb;
                LDSM_X4(ah[mi][0], ah[mi][1], ah[mi][2], ah[mi][3], tA + off);
            }
#pragma unroll
            for (int ni = 0; ni < 4; ni++) {
                uint32_t off = (b_row + ni * 8) * (LDS_ * 2) + b_colb + kb;
                LDSM_X2(bf[ni][0], bf[ni][1], tB + off);
            }
#pragma unroll
            for (int mi = 0; mi < 4; mi++)
#pragma unroll
                for (int ni = 0; ni < 4; ni++)
                    mma_f16(acc[mi][ni], ah[mi], bf[ni]);
        }
    }

    const int orow = m0 + wm + (lane >> 2);
    const int ocol = n0 + wn + 2 * (lane & 3);
#pragma unroll
    for (int mi = 0; mi < 4; mi++)
#pragma unroll
        for (int ni = 0; ni < 4; ni++) {
            float v0 = acc[mi][ni][0], v1 = acc[mi][ni][1];
            float v2 = acc[mi][ni][2], v3 = acc[mi][ni][3];
            if (mode == 1) {
                v0 = v0 / (1.f + expf(-v0));
                v1 = v1 / (1.f + expf(-v1));
                v2 = v2 / (1.f + expf(-v2));
                v3 = v3 / (1.f + expf(-v3));
            }
            float* p0 = C + (size_t)(orow + mi * 16) * D_ + ocol + ni * 8;
            float* p1 = C + (size_t)(orow + mi * 16 + 8) * D_ + ocol + ni * 8;
            *(float2*)p0 = make_float2(v0, v1);
            *(float2*)p1 = make_float2(v2, v3);
        }
}

// ========== beta projection: cp.async double-buffered tiled GEMM ===========
__global__ void __launch_bounds__(256) beta_gemm(const float* __restrict__ X,
                                                 const float* __restrict__ Wb,
                                                 float* __restrict__ beta) {
    __shared__ float Xs[2][16][132];
    __shared__ float Ws[2][128][16];
    const int m0 = blockIdx.x * 16;
    const int tid = threadIdx.x;
    const int row = tid >> 4, n = tid & 15;
    const uint32_t xb = smem_u32(&Xs[0][0][0]);
    const uint32_t wb = smem_u32(&Ws[0][0][0]);

    auto load_tile = [&](int buf, int kt) {
        const uint32_t xs = xb + buf * (16 * 132 * 4);
        const uint32_t ws = wb + buf * (128 * 16 * 4);
#pragma unroll
        for (int i = tid; i < 512; i += 256) {
            int r = i >> 5, c16 = i & 31;
            cp16(xs + r * 528 + c16 * 16, X + (size_t)(m0 + r) * D_ + kt + c16 * 4);
        }
#pragma unroll
        for (int i = tid; i < 512; i += 256) {
            int r = i >> 2, cc = i & 3;
            cp16(ws + r * 64 + cc * 16, Wb + (size_t)(kt + r) * H_ + cc * 4);
        }
        CP_COMMIT();
    };

    float acc = 0.f;
    load_tile(0, 0);
    for (int t = 0; t < 16; t++) {
        if (t + 1 < 16) load_tile((t + 1) & 1, (t + 1) * 128);
        else            CP_COMMIT();
        CP_WAIT(1);
        __syncthreads();
        const int buf = t & 1;
#pragma unroll 16
        for (int k = 0; k < 128; k++) acc += Xs[buf][row][k] * Ws[buf][k][n];
        __syncthreads();
    }
    beta[(size_t)(m0 + row) * H_ + n] = 1.f / (1.f + expf(-acc));
}

// ================= PRE: l2norm fused + per-chunk WY precompute ==============
__global__ void __launch_bounds__(128) pre_chunk(
    const float* __restrict__ q, const float* __restrict__ k,
    const float* __restrict__ v, const float* __restrict__ beta,
    float* __restrict__ W0g,
    __nv_bfloat16* __restrict__ TKh, __nv_bfloat16* __restrict__ TKl,
    __nv_bfloat16* __restrict__ Qh,  __nv_bfloat16* __restrict__ Ql,
    __nv_bfloat16* __restrict__ KTh, __nv_bfloat16* __restrict__ KTl,
    __nv_bfloat16* __restrict__ Ph,  __nv_bfloat16* __restrict__ Pl) {
    extern __shared__ float sm[];
    float* Kc  = sm;               // [32][128]
    float* Qc  = Kc + 32 * 128;    // [32][128]
    float* X   = Qc + 32 * 128;    // [32][256]  [bV | bK]
    float* Asm = X + 32 * 256;     // [32][32]
    float* bsm = Asm + 32 * 32;    // [32]

    const int ch = blockIdx.x;
    const int c  = ch & (NC_ - 1);
    const int bh = ch >> 6;
    const int b  = bh >> 4;
    const int h  = bh & 15;
    const int t0 = c * C_;
    const int tid = threadIdx.x;
    const size_t base0 = (size_t)b * L_ * D_ + (size_t)h * DH_;

    if (tid < 32) bsm[tid] = beta[((size_t)b * L_ + t0 + tid) * H_ + h];
    for (int i = tid; i < 32 * 32; i += 128) {
        int r = i >> 5, c4 = (i & 31) * 4;
        const size_t g = base0 + (size_t)(t0 + r) * D_ + c4;
        *(float4*)(Kc + r * 128 + c4) = *(const float4*)(k + g);
        *(float4*)(Qc + r * 128 + c4) = *(const float4*)(q + g);
        *(float4*)(X + r * 256 + c4)  = *(const float4*)(v + g);
    }
    __syncthreads();

    {
        const int w = tid >> 5, lane = tid & 31;
#pragma unroll
        for (int r = w * 8; r < w * 8 + 8; r++) {
            float4 kv = *(float4*)(Kc + r * 128 + lane * 4);
            float4 qv = *(float4*)(Qc + r * 128 + lane * 4);
            float sk = kv.x * kv.x + kv.y * kv.y + kv.z * kv.z + kv.w * kv.w;
            float sq = qv.x * qv.x + qv.y * qv.y + qv.z * qv.z + qv.w * qv.w;
#pragma unroll
            for (int off = 16; off; off >>= 1) {
                sk += __shfl_xor_sync(0xffffffffu, sk, off);
                sq += __shfl_xor_sync(0xffffffffu, sq, off);
            }
            float ik = 1.0f / fmaxf(sqrtf(sk), 1e-12f);
            float iq = 0.08838834764831845f / fmaxf(sqrtf(sq), 1e-12f);
            kv.x *= ik; kv.y *= ik; kv.z *= ik; kv.w *= ik;
            qv.x *= iq; qv.y *= iq; qv.z *= iq; qv.w *= iq;
            *(float4*)(Kc + r * 128 + lane * 4) = kv;
            *(float4*)(Qc + r * 128 + lane * 4) = qv;
        }
    }
    __syncthreads();

    for (int i = tid; i < 32 * 32; i += 128) {
        int r = i >> 5, c4 = (i & 31) * 4;
        float bt = bsm[r];
        float4 kv = *(float4*)(Kc + r * 128 + c4);
        kv.x *= bt; kv.y *= bt; kv.z *= bt; kv.w *= bt;
        *(float4*)(X + r * 256 + 128 + c4) = kv;
        float4 vv = *(float4*)(X + r * 256 + c4);
        vv.x *= bt; vv.y *= bt; vv.z *= bt; vv.w *= bt;
        *(float4*)(X + r * 256 + c4) = vv;
    }

    const int i_ = tid >> 2, j0 = (tid & 3) * 8;
    float accA[8], accP[8];
#pragma unroll
    for (int e = 0; e < 8; e++) { accA[e] = 0.f; accP[e] = 0.f; }
    for (int d4 = 0; d4 < 128; d4 += 4) {
        float4 ki = *(const float4*)(Kc + i_ * 128 + d4);
        float4 qi = *(const float4*)(Qc + i_ * 128 + d4);
#pragma unroll
        for (int e = 0; e < 8; e++) {
            float4 kj = *(const float4*)(Kc + (j0 + e) * 128 + d4);
            accA[e] += ki.x * kj.x + ki.y * kj.y + ki.z * kj.z + ki.w * kj.w;
            accP[e] += qi.x * kj.x + qi.y * kj.y + qi.z * kj.z + qi.w * kj.w;
        }
    }
    const float bi = bsm[i_];
#pragma unroll
    for (int e = 0; e < 8; e++) {
        int j = j0 + e;
        Asm[i_ * 32 + j] = (j < i_) ? bi * accA[e] : 0.f;
        float pv = (j <= i_) ? accP[e] : 0.f;
        __nv_bfloat16 phv = __float2bfloat16(pv);
        Ph[(size_t)ch * 1024 + i_ * 32 + j] = phv;
        Pl[(size_t)ch * 1024 + i_ * 32 + j] = __float2bfloat16(pv - __bfloat162float(phv));
    }
    __syncthreads();

    for (int i = 1; i < 32; i++) {
        float f0 = 0.f, f1 = 0.f;
        for (int j = 0; j < i; j++) {
            float a = Asm[i * 32 + j];
            f0 += a * X[j * 256 + tid];
            f1 += a * X[j * 256 + 128 + tid];
        }
        X[i * 256 + tid]       -= f0;
        X[i * 256 + 128 + tid] -= f1;
        __syncthreads();
    }

    for (int i = tid; i < 32 * 128; i += 128) {
        int n = i >> 7, m = i & 127;
        W0g[(size_t)ch * 4096 + i] = X[n * 256 + m];
        float tkv = X[n * 256 + 128 + m];
        __nv_bfloat16 th_ = __float2bfloat16(tkv);
        TKh[(size_t)ch * 4096 + i] = th_;
        TKl[(size_t)ch * 4096 + i] = __float2bfloat16(tkv - __bfloat162float(th_));
        float qv = Qc[n * 128 + m];
        __nv_bfloat16 qh_ = __float2bfloat16(qv);
        Qh[(size_t)ch * 4096 + i] = qh_;
        Ql[(size_t)ch * 4096 + i] = __float2bfloat16(qv - __bfloat162float(qh_));
    }
#pragma unroll
    for (int n = 0; n < 32; n++) {
        float kv = Kc[n * 128 + tid];
        __nv_bfloat16 kh_ = __float2bfloat16(kv);
        KTh[(size_t)ch * 4096 + tid * 32 + n] = kh_;
        KTl[(size_t)ch * 4096 + tid * 32 + n] = __float2bfloat16(kv - __bfloat162float(kh_));
    }
}

// ====== SEQ: dv-split x4, fused S-sweep (steps 1+2 share S fragment loads) ==
#define SST 272
#define WST 80
#define OS_SHI 0
#define OS_SLO 8704
#define OS_WTH 17408
#define OS_WTL 19968
#define OS_CS  22528
#define OS_OPS 22784
#define OB_TKH 0
#define OB_TKL 8704
#define OB_QH  17408
#define OB_QL  26112
#define OB_KTH 34816
#define OB_KTL 45056
#define OB_PH  55296
#define OB_PL  57856
#define OB_W0  60416
#define OB_SIZE 64512
#define SEQ_SMEM (OS_OPS + 2 * OB_SIZE)

__device__ __forceinline__ void seq_load_ops(uint32_t ob, size_t ch, int dvq, int tid,
    const float* W0g,
    const __nv_bfloat16* TKh, const __nv_bfloat16* TKl,
    const __nv_bfloat16* Qh,  const __nv_bfloat16* Ql,
    const __nv_bfloat16* KTh, const __nv_bfloat16* KTl,
    const __nv_bfloat16* Ph,  const __nv_bfloat16* Pl) {
    for (int i = tid; i < 512; i += 256) {
        int r = i >> 4, q = i & 15;
        size_t g = ch * 4096 + (size_t)r * 128 + q * 8;
        cp16(ob + OB_TKH + r * SST + q * 16, TKh + g);
        cp16(ob + OB_TKL + r * SST + q * 16, TKl + g);
        cp16(ob + OB_QH  + r * SST + q * 16, Qh + g);
        cp16(ob + OB_QL  + r * SST + q * 16, Ql + g);
    }
    for (int i = tid; i < 512; i += 256) {
        int r = i >> 2, q = i & 3;
        size_t g = ch * 4096 + (size_t)r * 32 + q * 8;
        cp16(ob + OB_KTH + r * WST + q * 16, KTh + g);
        cp16(ob + OB_KTL + r * WST + q * 16, KTl + g);
    }
    if (tid < 128) {
        int r = tid >> 2, q = tid & 3;
        size_t g = ch * 1024 + (size_t)r * 32 + q * 8;
        cp16(ob + OB_PH + r * WST + q * 16, Ph + g);
        cp16(ob + OB_PL + r * WST + q * 16, Pl + g);
    }
    {
        int r = tid >> 3, q = tid & 7;
        cp16(ob + OB_W0 + r * 128 + q * 16,
             W0g + ch * 4096 + (size_t)r * 128 + dvq * 32 + q * 4);
    }
    CP_COMMIT();
}

__global__ void __launch_bounds__(256, 1) seq_chunk(
    const float* __restrict__ W0g,
    const __nv_bfloat16* __restrict__ TKh, const __nv_bfloat16* __restrict__ TKl,
    const __nv_bfloat16* __restrict__ Qh,  const __nv_bfloat16* __restrict__ Ql,
    const __nv_bfloat16* __restrict__ KTh, const __nv_bfloat16* __restrict__ KTl,
    const __nv_bfloat16* __restrict__ Ph,  const __nv_bfloat16* __restrict__ Pl,
    const float* __restrict__ wnorm, float* __restrict__ o,
    float* __restrict__ oss) {
    extern __shared__ char smraw[];
    const int bh  = blockIdx.x >> 2;
    const int dvq = blockIdx.x & 3;
    const int b = bh >> 4, h = bh & 15;
    const int tid = threadIdx.x, wid = tid >> 5, lane = tid & 31;
    const uint32_t sb = smem_u32(smraw);
    float* colsum = (float*)(smraw + OS_CS);

    seq_load_ops(sb + OS_OPS, (size_t)bh * NC_, dvq, tid,
                 W0g, TKh, TKl, Qh, Ql, KTh, KTl, Ph, Pl);
    for (int i = tid; i < OS_OPS / 16; i += 256)
        ((uint4*)smraw)[i] = make_uint4(0, 0, 0, 0);

    float Sfr[4][4];
#pragma unroll
    for (int ni = 0; ni < 4; ni++)
#pragma unroll
        for (int e = 0; e < 4; e++) Sfr[ni][e] = 0.f;

    const int wm   = (wid & 1) * 16;
    const int tg   = wid >> 1;
    const int wn8  = tg * 8;
    const int wn32 = tg * 32;
    const int a_r = lane & 15, a_cB = (lane >> 4) << 4;
    const int b_r = lane & 7,  b_cB = ((lane >> 3) & 1) << 4;
    const int fr = lane >> 2, fc = (lane & 3) * 2;

    float wnr[2];
#pragma unroll
    for (int pp = 0; pp < 2; pp++)
        wnr[pp] = wnorm[dvq * 32 + wm + pp * 8 + fr];

    for (int c = 0; c < NC_; c++) {
        const size_t ch = (size_t)bh * NC_ + c;
        const int cb = c & 1;
        const uint32_t ob = sb + OS_OPS + cb * OB_SIZE;
        float* W0s = (float*)(smraw + OS_OPS + cb * OB_SIZE + OB_W0);

        __syncthreads();
        if (c + 1 < NC_)
            seq_load_ops(sb + OS_OPS + (1 - cb) * OB_SIZE, ch + 1, dvq, tid,
                         W0g, TKh, TKl, Qh, Ql, KTh, KTl, Ph, Pl);
        else
            CP_COMMIT();
        CP_WAIT(1);
        __syncthreads();

        // ---- fused S-sweep: acc = Ssm @ TK^T, oacc = Ssm @ Q^T (shared ah/al) ----
        float acc[4], oacc[4];
#pragma unroll
        for (int e = 0; e < 4; e++) { acc[e] = 0.f; oacc[e] = 0.f; }
#pragma unroll
        for (int ks = 0; ks < 8; ks++) {
            uint32_t ah[4], al[4], bt_h[2], bt_l[2], bq_h[2], bq_l[2];
            uint32_t offa = (wm + a_r) * SST + a_cB + ks * 32;
            LDSM_X4(ah[0], ah[1], ah[2], ah[3], sb + OS_SHI + offa);
            LDSM_X4(al[0], al[1], al[2], al[3], sb + OS_SLO + offa);
            uint32_t offb = (wn8 + b_r) * SST + b_cB + ks * 32;
            LDSM_X2(bt_h[0], bt_h[1], ob + OB_TKH + offb);
            LDSM_X2(bt_l[0], bt_l[1], ob + OB_TKL + offb);
            LDSM_X2(bq_h[0], bq_h[1], ob + OB_QH + offb);
            LDSM_X2(bq_l[0], bq_l[1], ob + OB_QL + offb);
            mma_bf16(acc,  ah, bt_h);
            mma_bf16(acc,  ah, bt_l);
            mma_bf16(acc,  al, bt_h);
            mma_bf16(oacc, ah, bq_h);
            mma_bf16(oacc, ah, bq_l);
            mma_bf16(oacc, al, bq_h);
        }
        // Wt = W0^T - acc  -> smem (hi/lo)
#pragma unroll
        for (int pp = 0; pp < 2; pp++) {
            int m = wm + fr + pp * 8;
            int n0 = wn8 + fc;
            float v0 = W0s[n0 * 32 + m] - acc[pp * 2 + 0];
            float v1 = W0s[(n0 + 1) * 32 + m] - acc[pp * 2 + 1];
            uint32_t lo, hi = pack_split(v0, v1, lo);
            *(uint32_t*)(smraw + OS_WTH + m * WST + n0 * 2) = hi;
            *(uint32_t*)(smraw + OS_WTL + m * WST + n0 * 2) = lo;
        }
        __syncthreads();

        // ---- Ot += Wt @ P^T ----
#pragma unroll
        for (int ks = 0; ks < 2; ks++) {
            uint32_t ah[4], al[4], bhf[2], blf[2];
            uint32_t offa = (wm + a_r) * WST + a_cB + ks * 32;
            LDSM_X4(ah[0], ah[1], ah[2], ah[3], sb + OS_WTH + offa);
            LDSM_X4(al[0], al[1], al[2], al[3], sb + OS_WTL + offa);
            uint32_t offb = (wn8 + b_r) * WST + b_cB + ks * 32;
            LDSM_X2(bhf[0], bhf[1], ob + OB_PH + offb);
            LDSM_X2(blf[0], blf[1], ob + OB_PL + offb);
            mma_bf16(oacc, ah, bhf);
            mma_bf16(oacc, ah, blf);
            mma_bf16(oacc, al, bhf);
        }
        {
            float s0 = oacc[0] * oacc[0] + oacc[2] * oacc[2];
            float s1 = oacc[1] * oacc[1] + oacc[3] * oacc[3];
#pragma unroll
            for (int off = 4; off <= 16; off <<= 1) {
                s0 += __shfl_xor_sync(0xffffffffu, s0, off);
                s1 += __shfl_xor_sync(0xffffffffu, s1, off);
            }
            if (lane < 4) {
                atomicAdd(&colsum[cb * 32 + wn8 + 2 * lane], s0);
                atomicAdd(&colsum[cb * 32 + wn8 + 2 * lane + 1], s1);
            }
        }
        __syncthreads();

        {
            const size_t obase = (size_t)b * L_ * D_ + (size_t)h * DH_ + (size_t)(c * C_) * D_
                               + dvq * 32;
            int n0 = wn8 + fc;
#pragma unroll
            for (int pp = 0; pp < 2; pp++) {
                int m = wm + fr + pp * 8;
                o[obase + (size_t)n0 * D_ + m] = oacc[pp * 2] * wnr[pp];
                o[obase + (size_t)(n0 + 1) * D_ + m] = oacc[pp * 2 + 1] * wnr[pp];
            }
            if (tid < 32) {
                oss[(size_t)dvq * (M_ * H_) + ((size_t)b * L_ + c * C_ + tid) * H_ + h]
                    = colsum[cb * 32 + tid];
                colsum[(1 - cb) * 32 + tid] = 0.f;
            }
        }

        // ---- step 3: Ssm += Wt @ K ----
#pragma unroll
        for (int ks = 0; ks < 2; ks++) {
            uint32_t ah[4], al[4];
            uint32_t offa = (wm + a_r) * WST + a_cB + ks * 32;
            LDSM_X4(ah[0], ah[1], ah[2], ah[3], sb + OS_WTH + offa);
            LDSM_X4(al[0], al[1], al[2], al[3], sb + OS_WTL + offa);
#pragma unroll
            for (int ni = 0; ni < 4; ni++) {
                uint32_t bhf[2], blf[2];
                uint32_t offb = (wn32 + ni * 8 + b_r) * WST + b_cB + ks * 32;
                LDSM_X2(bhf[0], bhf[1], ob + OB_KTH + offb);
                LDSM_X2(blf[0], blf[1], ob + OB_KTL + offb);
                mma_bf16(Sfr[ni], ah, bhf);
                mma_bf16(Sfr[ni], ah, blf);
                mma_bf16(Sfr[ni], al, bhf);
            }
        }
#pragma unroll
        for (int ni = 0; ni < 4; ni++)
#pragma unroll
            for (int pp = 0; pp < 2; pp++) {
                int m = wm + fr + pp * 8;
                int n0 = wn32 + ni * 8 + fc;
                uint32_t lo, hi = pack_split(Sfr[ni][pp * 2], Sfr[ni][pp * 2 + 1], lo);
                *(uint32_t*)(smraw + OS_SHI + m * SST + n0 * 2) = hi;
                *(uint32_t*)(smraw + OS_SLO + m * SST + n0 * 2) = lo;
            }
    }
}

// ================= launch =================
extern "C" void kernel_launch(void* const* d_in, const int* in_sizes, int n_in,
                              void* d_out, int out_size) {
    const float* X  = (const float*)d_in[0];
    const float* Wq = (const float*)d_in[1];
    const float* Wk = (const float*)d_in[2];
    const float* Wv = (const float*)d_in[3];
    const float* Wb = (const float*)d_in[4];
    const float* wn = (const float*)d_in[5];
    const float* Wo = (const float*)d_in[6];
    float* out = (float*)d_out;

    float *gq, *gk, *gv, *go, *gb, *gW0, *gss;
    __half *ahi, *wt;
    __nv_bfloat16 *tkh, *tkl, *qch, *qcl, *kth, *ktl, *ph, *pl;
    cudaGetSymbolAddress((void**)&gq, g_q);
    cudaGetSymbolAddress((void**)&gk, g_k);
    cudaGetSymbolAddress((void**)&gv, g_v);
    cudaGetSymbolAddress((void**)&go, g_o);
    cudaGetSymbolAddress((void**)&gb, g_beta);
    cudaGetSymbolAddress((void**)&gss, g_ss);
    cudaGetSymbolAddress((void**)&ahi, g_Ahi);
    cudaGetSymbolAddress((void**)&wt, g_Wt);
    cudaGetSymbolAddress((void**)&gW0, g_W0);
    cudaGetSymbolAddress((void**)&tkh, g_TKh);
    cudaGetSymbolAddress((void**)&tkl, g_TKl);
    cudaGetSymbolAddress((void**)&qch, g_Qch);
    cudaGetSymbolAddress((void**)&qcl, g_Qcl);
    cudaGetSymbolAddress((void**)&kth, g_KTh);
    cudaGetSymbolAddress((void**)&ktl, g_KTl);
    cudaGetSymbolAddress((void**)&ph, g_Ph);
    cudaGetSymbolAddress((void**)&pl, g_Pl);

    cudaFuncSetAttribute(gemm_f16, cudaFuncAttributeMaxDynamicSharedMemorySize, SMEM_DYN);
    cudaFuncSetAttribute(pre_chunk, cudaFuncAttributeMaxDynamicSharedMemorySize, 69760);
    cudaFuncSetAttribute(seq_chunk, cudaFuncAttributeMaxDynamicSharedMemorySize, SEQ_SMEM);

    const int NSPLIT = M_ * D_ / 4 / 256;

    split_rows<<<NSPLIT, 256>>>((const float4*)X, (uint2*)ahi);
    split_transpose<<<dim3(D_ / 32, D_ / 32, 4), dim3(32, 8)>>>(Wq, Wk, Wv, Wo, wt);

    GemmArgs qa;
    qa.Bw[0] = wt;
    qa.Bw[1] = wt + (size_t)D_ * D_;
    qa.Bw[2] = wt + (size_t)2 * D_ * D_;
    qa.C[0] = gq; qa.C[1] = gk; qa.C[2] = gv;
    qa.mode[0] = 0; qa.mode[1] = 0; qa.mode[2] = 1;
    gemm_f16<<<dim3(D_ / BN, M_ / BM, 3), 256, SMEM_DYN>>>(ahi, qa);

    beta_gemm<<<M_ / 16, 256>>>(X, Wb, gb);

    pre_chunk<<<NCH_, 128, 69760>>>(gq, gk, gv, gb, gW0, tkh, tkl, qch, qcl, kth, ktl, ph, pl);
    seq_chunk<<<4 * B_ * H_, 256, SEQ_SMEM>>>(gW0, tkh, tkl, qch, qcl, kth, ktl, ph, pl, wn, go, gss);

    split_rows_norm<<<NSPLIT, 256>>>((const float4*)go, (uint2*)ahi, gss);
    GemmArgs oa;
    oa.Bw[0] = wt + (size_t)3 * D_ * D_;
    oa.Bw[1] = oa.Bw[0];
    oa.Bw[2] = oa.Bw[0];
    oa.C[0] = out; oa.C[1] = out; oa.C[2] = out;
    oa.mode[0] = 0; oa.mode[1] = 0; oa.mode[2] = 0;
    gemm_f16<<<dim3(D_ / BN, M_ / BM, 1), 256, SMEM_DYN>>>(ahi, oa);
}

// round 17
// speedup vs baseline: 1.0767x; 1.0072x over previous
#include <cuda_runtime.h>
#include <cuda_bf16.h>
#include <cuda_fp16.h>
#include <math.h>
#include <stdint.h>

#define B_  2
#define L_  2048
#define D_  2048
#define H_  16
#define DH_ 128
#define M_  (B_ * L_)   // 4096
#define C_  32          // chunk length
#define NC_ (L_ / C_)   // 64 chunks per (b,h)
#define NCH_ (B_ * H_ * NC_)  // 2048 chunk-heads

// ================= scratch (device globals; no allocations) =================
__device__ float g_q[M_ * D_];
__device__ float g_k[M_ * D_];
__device__ float g_v[M_ * D_];
__device__ float g_o[M_ * D_];
__device__ float g_beta[M_ * H_];
__device__ float g_ss[4 * M_ * H_];      // partial sumsq per dv-quarter
__device__ __half g_Ahi[M_ * D_];        // fp16 A operand (X, then normalized o)
__device__ __half g_Wt[4 * D_ * D_];     // transposed weights [N,K] fp16, order q,k,v,o
// chunked delta-rule precompute (bf16 3-combo)
__device__ float g_W0[NCH_ * C_ * DH_];
__device__ __nv_bfloat16 g_TKh[NCH_ * C_ * DH_];
__device__ __nv_bfloat16 g_TKl[NCH_ * C_ * DH_];
__device__ __nv_bfloat16 g_Qch[NCH_ * C_ * DH_];
__device__ __nv_bfloat16 g_Qcl[NCH_ * C_ * DH_];
__device__ __nv_bfloat16 g_KTh[NCH_ * DH_ * C_];
__device__ __nv_bfloat16 g_KTl[NCH_ * DH_ * C_];
__device__ __nv_bfloat16 g_Ph[NCH_ * C_ * C_];
__device__ __nv_bfloat16 g_Pl[NCH_ * C_ * C_];

// ================= helpers =================
__device__ __forceinline__ uint32_t smem_u32(const void* p) {
    uint32_t a;
    asm("{ .reg .u64 t; cvta.to.shared.u64 t, %1; cvt.u32.u64 %0, t; }" : "=r"(a) : "l"(p));
    return a;
}
__device__ __forceinline__ void cp16(uint32_t dst, const void* src) {
    asm volatile("cp.async.cg.shared.global [%0], [%1], 16;" :: "r"(dst), "l"(src));
}
#define CP_COMMIT() asm volatile("cp.async.commit_group;" ::: "memory")
#define CP_WAIT(n)  asm volatile("cp.async.wait_group %0;" :: "n"(n) : "memory")

#define LDSM_X4(r0, r1, r2, r3, addr)                                            \
    asm volatile("ldmatrix.sync.aligned.m8n8.x4.shared.b16 {%0,%1,%2,%3}, [%4];" \
        : "=r"(r0), "=r"(r1), "=r"(r2), "=r"(r3) : "r"(addr))
#define LDSM_X2(r0, r1, addr)                                                    \
    asm volatile("ldmatrix.sync.aligned.m8n8.x2.shared.b16 {%0,%1}, [%2];"       \
        : "=r"(r0), "=r"(r1) : "r"(addr))

__device__ __forceinline__ void mma_bf16(float* d, const uint32_t* a, const uint32_t* b) {
    asm volatile(
        "mma.sync.aligned.m16n8k16.row.col.f32.bf16.bf16.f32 "
        "{%0,%1,%2,%3}, {%4,%5,%6,%7}, {%8,%9}, {%0,%1,%2,%3};"
        : "+f"(d[0]), "+f"(d[1]), "+f"(d[2]), "+f"(d[3])
        : "r"(a[0]), "r"(a[1]), "r"(a[2]), "r"(a[3]), "r"(b[0]), "r"(b[1]));
}
__device__ __forceinline__ void mma_f16(float* d, const uint32_t* a, const uint32_t* b) {
    asm volatile(
        "mma.sync.aligned.m16n8k16.row.col.f32.f16.f16.f32 "
        "{%0,%1,%2,%3}, {%4,%5,%6,%7}, {%8,%9}, {%0,%1,%2,%3};"
        : "+f"(d[0]), "+f"(d[1]), "+f"(d[2]), "+f"(d[3])
        : "r"(a[0]), "r"(a[1]), "r"(a[2]), "r"(a[3]), "r"(b[0]), "r"(b[1]));
}
__device__ __forceinline__ uint32_t pack_split(float v0, float v1, uint32_t& lo) {
    __nv_bfloat16 h0 = __float2bfloat16(v0), h1 = __float2bfloat16(v1);
    __nv_bfloat16 l0 = __float2bfloat16(v0 - __bfloat162float(h0));
    __nv_bfloat16 l1 = __float2bfloat16(v1 - __bfloat162float(h1));
    lo = ((uint32_t)__bfloat16_as_ushort(l1) << 16) | __bfloat16_as_ushort(l0);
    return ((uint32_t)__bfloat16_as_ushort(h1) << 16) | __bfloat16_as_ushort(h0);
}

// ================= fp32 -> fp16 =================
__global__ void __launch_bounds__(256) split_rows(const float4* __restrict__ X,
                                                  uint2* __restrict__ hi) {
    int i = blockIdx.x * 256 + threadIdx.x;
    float4 x = X[i];
    __half h0 = __float2half_rn(x.x), h1 = __float2half_rn(x.y);
    __half h2 = __float2half_rn(x.z), h3 = __float2half_rn(x.w);
    uint2 hv;
    hv.x = ((uint32_t)__half_as_ushort(h1) << 16) | __half_as_ushort(h0);
    hv.y = ((uint32_t)__half_as_ushort(h3) << 16) | __half_as_ushort(h2);
    hi[i] = hv;
}

// fp16 convert + deferred RMSNorm scale for o
__global__ void __launch_bounds__(256) split_rows_norm(const float4* __restrict__ X,
                                                       uint2* __restrict__ hi,
                                                       const float* __restrict__ ss) {
    int i = blockIdx.x * 256 + threadIdx.x;
    int m = i >> 9;
    int h = (i & 511) >> 5;
    size_t idx = (size_t)m * H_ + h;
    float s = ss[idx] + ss[(size_t)M_ * H_ + idx]
            + ss[(size_t)2 * M_ * H_ + idx] + ss[(size_t)3 * M_ * H_ + idx];
    float r = rsqrtf(s * (1.0f / 128.0f) + 1e-5f);
    float4 x = X[i];
    x.x *= r; x.y *= r; x.z *= r; x.w *= r;
    __half h0 = __float2half_rn(x.x), h1 = __float2half_rn(x.y);
    __half h2 = __float2half_rn(x.z), h3 = __float2half_rn(x.w);
    uint2 hv;
    hv.x = ((uint32_t)__half_as_ushort(h1) << 16) | __half_as_ushort(h0);
    hv.y = ((uint32_t)__half_as_ushort(h3) << 16) | __half_as_ushort(h2);
    hi[i] = hv;
}

// transpose weights: W[k][n] fp32 -> Wt[n][k] fp16 (grid.z selects matrix)
__global__ void __launch_bounds__(256) split_transpose(
    const float* __restrict__ W0, const float* __restrict__ W1,
    const float* __restrict__ W2, const float* __restrict__ W3,
    __half* __restrict__ wt) {
    __shared__ float t[32][33];
    const float* W = (blockIdx.z == 0) ? W0 : (blockIdx.z == 1) ? W1
                   : (blockIdx.z == 2) ? W2 : W3;
    __half* ho = wt + (size_t)blockIdx.z * D_ * D_;
    const int n = blockIdx.x * 32 + threadIdx.x;
    const int k0 = blockIdx.y * 32;
#pragma unroll
    for (int i = threadIdx.y; i < 32; i += 8)
        t[i][threadIdx.x] = W[(size_t)(k0 + i) * D_ + n];
    __syncthreads();
#pragma unroll
    for (int i = threadIdx.y; i < 32; i += 8) {
        const int nn = blockIdx.x * 32 + i;
        ho[(size_t)nn * D_ + k0 + threadIdx.x] = __float2half_rn(t[threadIdx.x][i]);
    }
}

// ====== fp16 single-combo GEMM: R13 config (BK=32, 3-stage, 2 CTAs/SM) ======
#define BM 128
#define BN 128
#define BK 32
#define LDS_ 40
#define TILE_B (128 * LDS_ * 2)       // 10240
#define STAGE_B (2 * TILE_B)          // A, B = 20480
#define NSTAGE 3
#define SMEM_DYN (NSTAGE * STAGE_B)   // 61440
#define NCHUNK (D_ / BK)

struct GemmArgs {
    const __half* Bw[3];
    float* C[3];
    int mode[3];
};

__device__ __forceinline__ void load_chunk(uint32_t sbase, int stage,
    const __half* Ahi, const __half* Bw,
    int m0, int n0, int kc, int tid) {
    const int r  = tid >> 1;
    const int c0 = (tid & 1) * 2;
    const uint32_t st = sbase + stage * STAGE_B;
    const size_t koff = (size_t)kc * BK;
    const __half* srcs[2] = {
        Ahi + (size_t)(m0 + r) * D_ + koff,
        Bw  + (size_t)(n0 + r) * D_ + koff };
#pragma unroll
    for (int t = 0; t < 2; t++) {
        uint32_t rowb = st + t * TILE_B + r * (LDS_ * 2);
        cp16(rowb + (c0 + 0) * 16, srcs[t] + (c0 + 0) * 8);
        cp16(rowb + (c0 + 1) * 16, srcs[t] + (c0 + 1) * 8);
    }
    CP_COMMIT();
}

__global__ void __launch_bounds__(256, 2) gemm_f16(
    const __half* __restrict__ Ahi, GemmArgs args) {
    extern __shared__ char smem_raw[];
    const int z = blockIdx.z;
    const __half* Bw = args.Bw[z];
    float* C = args.C[z];
    const int mode = args.mode[z];

    const int m0 = blockIdx.y * BM;
    const int n0 = blockIdx.x * BN;
    const int tid = threadIdx.x;
    const int wid = tid >> 5;
    const int lane = tid & 31;
    const int wm = (wid & 1) * 64;
    const int wn = (wid >> 1) * 32;
    const uint32_t sbase = smem_u32(smem_raw);

    const uint32_t a_row  = wm + (lane & 15);
    const uint32_t a_colb = ((lane >> 4) << 4);
    const uint32_t b_row  = wn + (lane & 7);
    const uint32_t b_colb = (((lane >> 3) & 1) << 4);

    float acc[4][4][4];
#pragma unroll
    for (int mi = 0; mi < 4; mi++)
#pragma unroll
        for (int ni = 0; ni < 4; ni++)
#pragma unroll
            for (int t = 0; t < 4; t++) acc[mi][ni][t] = 0.f;

    load_chunk(sbase, 0, Ahi, Bw, m0, n0, 0, tid);
    load_chunk(sbase, 1, Ahi, Bw, m0, n0, 1, tid);

    for (int c = 0; c < NCHUNK; c++) {
        CP_WAIT(1);
        __syncthreads();
        if (c + 2 < NCHUNK) {
            int s = (c + 2) % NSTAGE;
            load_chunk(sbase, s, Ahi, Bw, m0, n0, c + 2, tid);
        } else {
            CP_COMMIT();
        }

        const uint32_t st  = sbase + (c % NSTAGE) * STAGE_B;
        const uint32_t tA  = st;
        const uint32_t tB  = st + TILE_B;

#pragma unroll
        for (int ks = 0; ks < 2; ks++) {
            const uint32_t kb = ks * 32;
            uint32_t ah[4][4], bf[4][2];
#pragma unroll
            for (int mi = 0; mi < 4; mi++) {
                uint32_t off = (a_row + mi * 16) * (LDS_ * 2) + a_colb + kb;
                LDSM_X4(ah[mi][0], ah[mi][1], ah[mi][2], ah[mi][3], tA + off);
            }
#pragma unroll
            for (int ni = 0; ni < 4; ni++) {
                uint32_t off = (b_row + ni * 8) * (LDS_ * 2) + b_colb + kb;
                LDSM_X2(bf[ni][0], bf[ni][1], tB + off);
            }
#pragma unroll
            for (int mi = 0; mi < 4; mi++)
#pragma unroll
                for (int ni = 0; ni < 4; ni++)
                    mma_f16(acc[mi][ni], ah[mi], bf[ni]);
        }
    }

    const int orow = m0 + wm + (lane >> 2);
    const int ocol = n0 + wn + 2 * (lane & 3);
#pragma unroll
    for (int mi = 0; mi < 4; mi++)
#pragma unroll
        for (int ni = 0; ni < 4; ni++) {
            float v0 = acc[mi][ni][0], v1 = acc[mi][ni][1];
            float v2 = acc[mi][ni][2], v3 = acc[mi][ni][3];
            if (mode == 1) {
                v0 = v0 / (1.f + expf(-v0));
                v1 = v1 / (1.f + expf(-v1));
                v2 = v2 / (1.f + expf(-v2));
                v3 = v3 / (1.f + expf(-v3));
            }
            float* p0 = C + (size_t)(orow + mi * 16) * D_ + ocol + ni * 8;
            float* p1 = C + (size_t)(orow + mi * 16 + 8) * D_ + ocol + ni * 8;
            *(float2*)p0 = make_float2(v0, v1);
            *(float2*)p1 = make_float2(v2, v3);
        }
}

// ========== beta projection: cp.async double-buffered tiled GEMM ===========
__global__ void __launch_bounds__(256) beta_gemm(const float* __restrict__ X,
                                                 const float* __restrict__ Wb,
                                                 float* __restrict__ beta) {
    __shared__ float Xs[2][16][132];
    __shared__ float Ws[2][128][16];
    const int m0 = blockIdx.x * 16;
    const int tid = threadIdx.x;
    const int row = tid >> 4, n = tid & 15;
    const uint32_t xb = smem_u32(&Xs[0][0][0]);
    const uint32_t wb = smem_u32(&Ws[0][0][0]);

    auto load_tile = [&](int buf, int kt) {
        const uint32_t xs = xb + buf * (16 * 132 * 4);
        const uint32_t ws = wb + buf * (128 * 16 * 4);
#pragma unroll
        for (int i = tid; i < 512; i += 256) {
            int r = i >> 5, c16 = i & 31;
            cp16(xs + r * 528 + c16 * 16, X + (size_t)(m0 + r) * D_ + kt + c16 * 4);
        }
#pragma unroll
        for (int i = tid; i < 512; i += 256) {
            int r = i >> 2, cc = i & 3;
            cp16(ws + r * 64 + cc * 16, Wb + (size_t)(kt + r) * H_ + cc * 4);
        }
        CP_COMMIT();
    };

    float acc = 0.f;
    load_tile(0, 0);
    for (int t = 0; t < 16; t++) {
        if (t + 1 < 16) load_tile((t + 1) & 1, (t + 1) * 128);
        else            CP_COMMIT();
        CP_WAIT(1);
        __syncthreads();
        const int buf = t & 1;
#pragma unroll 16
        for (int k = 0; k < 128; k++) acc += Xs[buf][row][k] * Ws[buf][k][n];
        __syncthreads();
    }
    beta[(size_t)(m0 + row) * H_ + n] = 1.f / (1.f + expf(-acc));
}

// ================= PRE: l2norm fused + per-chunk WY precompute ==============
__global__ void __launch_bounds__(128) pre_chunk(
    const float* __restrict__ q, const float* __restrict__ k,
    const float* __restrict__ v, const float* __restrict__ beta,
    float* __restrict__ W0g,
    __nv_bfloat16* __restrict__ TKh, __nv_bfloat16* __restrict__ TKl,
    __nv_bfloat16* __restrict__ Qh,  __nv_bfloat16* __restrict__ Ql,
    __nv_bfloat16* __restrict__ KTh, __nv_bfloat16* __restrict__ KTl,
    __nv_bfloat16* __restrict__ Ph,  __nv_bfloat16* __restrict__ Pl) {
    extern __shared__ float sm[];
    float* Kc  = sm;               // [32][128]
    float* Qc  = Kc + 32 * 128;    // [32][128]
    float* X   = Qc + 32 * 128;    // [32][256]  [bV | bK]
    float* Asm = X + 32 * 256;     // [32][32]
    float* bsm = Asm + 32 * 32;    // [32]

    const int ch = blockIdx.x;
    const int c  = ch & (NC_ - 1);
    const int bh = ch >> 6;
    const int b  = bh >> 4;
    const int h  = bh & 15;
    const int t0 = c * C_;
    const int tid = threadIdx.x;
    const size_t base0 = (size_t)b * L_ * D_ + (size_t)h * DH_;

    if (tid < 32) bsm[tid] = beta[((size_t)b * L_ + t0 + tid) * H_ + h];
    for (int i = tid; i < 32 * 32; i += 128) {
        int r = i >> 5, c4 = (i & 31) * 4;
        const size_t g = base0 + (size_t)(t0 + r) * D_ + c4;
        *(float4*)(Kc + r * 128 + c4) = *(const float4*)(k + g);
        *(float4*)(Qc + r * 128 + c4) = *(const float4*)(q + g);
        *(float4*)(X + r * 256 + c4)  = *(const float4*)(v + g);
    }
    __syncthreads();

    {
        const int w = tid >> 5, lane = tid & 31;
#pragma unroll
        for (int r = w * 8; r < w * 8 + 8; r++) {
            float4 kv = *(float4*)(Kc + r * 128 + lane * 4);
            float4 qv = *(float4*)(Qc + r * 128 + lane * 4);
            float sk = kv.x * kv.x + kv.y * kv.y + kv.z * kv.z + kv.w * kv.w;
            float sq = qv.x * qv.x + qv.y * qv.y + qv.z * qv.z + qv.w * qv.w;
#pragma unroll
            for (int off = 16; off; off >>= 1) {
                sk += __shfl_xor_sync(0xffffffffu, sk, off);
                sq += __shfl_xor_sync(0xffffffffu, sq, off);
            }
            float ik = 1.0f / fmaxf(sqrtf(sk), 1e-12f);
            float iq = 0.08838834764831845f / fmaxf(sqrtf(sq), 1e-12f);
            kv.x *= ik; kv.y *= ik; kv.z *= ik; kv.w *= ik;
            qv.x *= iq; qv.y *= iq; qv.z *= iq; qv.w *= iq;
            *(float4*)(Kc + r * 128 + lane * 4) = kv;
            *(float4*)(Qc + r * 128 + lane * 4) = qv;
        }
    }
    __syncthreads();

    for (int i = tid; i < 32 * 32; i += 128) {
        int r = i >> 5, c4 = (i & 31) * 4;
        float bt = bsm[r];
        float4 kv = *(float4*)(Kc + r * 128 + c4);
        kv.x *= bt; kv.y *= bt; kv.z *= bt; kv.w *= bt;
        *(float4*)(X + r * 256 + 128 + c4) = kv;
        float4 vv = *(float4*)(X + r * 256 + c4);
        vv.x *= bt; vv.y *= bt; vv.z *= bt; vv.w *= bt;
        *(float4*)(X + r * 256 + c4) = vv;
    }

    const int i_ = tid >> 2, j0 = (tid & 3) * 8;
    float accA[8], accP[8];
#pragma unroll
    for (int e = 0; e < 8; e++) { accA[e] = 0.f; accP[e] = 0.f; }
    for (int d4 = 0; d4 < 128; d4 += 4) {
        float4 ki = *(const float4*)(Kc + i_ * 128 + d4);
        float4 qi = *(const float4*)(Qc + i_ * 128 + d4);
#pragma unroll
        for (int e = 0; e < 8; e++) {
            float4 kj = *(const float4*)(Kc + (j0 + e) * 128 + d4);
            accA[e] += ki.x * kj.x + ki.y * kj.y + ki.z * kj.z + ki.w * kj.w;
            accP[e] += qi.x * kj.x + qi.y * kj.y + qi.z * kj.z + qi.w * kj.w;
        }
    }
    const float bi = bsm[i_];
#pragma unroll
    for (int e = 0; e < 8; e++) {
        int j = j0 + e;
        Asm[i_ * 32 + j] = (j < i_) ? bi * accA[e] : 0.f;
        float pv = (j <= i_) ? accP[e] : 0.f;
        __nv_bfloat16 phv = __float2bfloat16(pv);
        Ph[(size_t)ch * 1024 + i_ * 32 + j] = phv;
        Pl[(size_t)ch * 1024 + i_ * 32 + j] = __float2bfloat16(pv - __bfloat162float(phv));
    }
    __syncthreads();

    for (int i = 1; i < 32; i++) {
        float f0 = 0.f, f1 = 0.f;
        for (int j = 0; j < i; j++) {
            float a = Asm[i * 32 + j];
            f0 += a * X[j * 256 + tid];
            f1 += a * X[j * 256 + 128 + tid];
        }
        X[i * 256 + tid]       -= f0;
        X[i * 256 + 128 + tid] -= f1;
        __syncthreads();
    }

    for (int i = tid; i < 32 * 128; i += 128) {
        int n = i >> 7, m = i & 127;
        W0g[(size_t)ch * 4096 + i] = X[n * 256 + m];
        float tkv = X[n * 256 + 128 + m];
        __nv_bfloat16 th_ = __float2bfloat16(tkv);
        TKh[(size_t)ch * 4096 + i] = th_;
        TKl[(size_t)ch * 4096 + i] = __float2bfloat16(tkv - __bfloat162float(th_));
        float qv = Qc[n * 128 + m];
        __nv_bfloat16 qh_ = __float2bfloat16(qv);
        Qh[(size_t)ch * 4096 + i] = qh_;
        Ql[(size_t)ch * 4096 + i] = __float2bfloat16(qv - __bfloat162float(qh_));
    }
#pragma unroll
    for (int n = 0; n < 32; n++) {
        float kv = Kc[n * 128 + tid];
        __nv_bfloat16 kh_ = __float2bfloat16(kv);
        KTh[(size_t)ch * 4096 + tid * 32 + n] = kh_;
        KTl[(size_t)ch * 4096 + tid * 32 + n] = __float2bfloat16(kv - __bfloat162float(kh_));
    }
}

// ====== SEQ: dv-split x4, fused S-sweep + fused Wt-sweep ====================
#define SST 272
#define WST 80
#define OS_SHI 0
#define OS_SLO 8704
#define OS_WTH 17408
#define OS_WTL 19968
#define OS_CS  22528
#define OS_OPS 22784
#define OB_TKH 0
#define OB_TKL 8704
#define OB_QH  17408
#define OB_QL  26112
#define OB_KTH 34816
#define OB_KTL 45056
#define OB_PH  55296
#define OB_PL  57856
#define OB_W0  60416
#define OB_SIZE 64512
#define SEQ_SMEM (OS_OPS + 2 * OB_SIZE)

__device__ __forceinline__ void seq_load_ops(uint32_t ob, size_t ch, int dvq, int tid,
    const float* W0g,
    const __nv_bfloat16* TKh, const __nv_bfloat16* TKl,
    const __nv_bfloat16* Qh,  const __nv_bfloat16* Ql,
    const __nv_bfloat16* KTh, const __nv_bfloat16* KTl,
    const __nv_bfloat16* Ph,  const __nv_bfloat16* Pl) {
    for (int i = tid; i < 512; i += 256) {
        int r = i >> 4, q = i & 15;
        size_t g = ch * 4096 + (size_t)r * 128 + q * 8;
        cp16(ob + OB_TKH + r * SST + q * 16, TKh + g);
        cp16(ob + OB_TKL + r * SST + q * 16, TKl + g);
        cp16(ob + OB_QH  + r * SST + q * 16, Qh + g);
        cp16(ob + OB_QL  + r * SST + q * 16, Ql + g);
    }
    for (int i = tid; i < 512; i += 256) {
        int r = i >> 2, q = i & 3;
        size_t g = ch * 4096 + (size_t)r * 32 + q * 8;
        cp16(ob + OB_KTH + r * WST + q * 16, KTh + g);
        cp16(ob + OB_KTL + r * WST + q * 16, KTl + g);
    }
    if (tid < 128) {
        int r = tid >> 2, q = tid & 3;
        size_t g = ch * 1024 + (size_t)r * 32 + q * 8;
        cp16(ob + OB_PH + r * WST + q * 16, Ph + g);
        cp16(ob + OB_PL + r * WST + q * 16, Pl + g);
    }
    {
        int r = tid >> 3, q = tid & 7;
        cp16(ob + OB_W0 + r * 128 + q * 16,
             W0g + ch * 4096 + (size_t)r * 128 + dvq * 32 + q * 4);
    }
    CP_COMMIT();
}

__global__ void __launch_bounds__(256, 1) seq_chunk(
    const float* __restrict__ W0g,
    const __nv_bfloat16* __restrict__ TKh, const __nv_bfloat16* __restrict__ TKl,
    const __nv_bfloat16* __restrict__ Qh,  const __nv_bfloat16* __restrict__ Ql,
    const __nv_bfloat16* __restrict__ KTh, const __nv_bfloat16* __restrict__ KTl,
    const __nv_bfloat16* __restrict__ Ph,  const __nv_bfloat16* __restrict__ Pl,
    const float* __restrict__ wnorm, float* __restrict__ o,
    float* __restrict__ oss) {
    extern __shared__ char smraw[];
    const int bh  = blockIdx.x >> 2;
    const int dvq = blockIdx.x & 3;
    const int b = bh >> 4, h = bh & 15;
    const int tid = threadIdx.x, wid = tid >> 5, lane = tid & 31;
    const uint32_t sb = smem_u32(smraw);
    float* colsum = (float*)(smraw + OS_CS);

    seq_load_ops(sb + OS_OPS, (size_t)bh * NC_, dvq, tid,
                 W0g, TKh, TKl, Qh, Ql, KTh, KTl, Ph, Pl);
    for (int i = tid; i < OS_OPS / 16; i += 256)
        ((uint4*)smraw)[i] = make_uint4(0, 0, 0, 0);

    float Sfr[4][4];
#pragma unroll
    for (int ni = 0; ni < 4; ni++)
#pragma unroll
        for (int e = 0; e < 4; e++) Sfr[ni][e] = 0.f;

    const int wm   = (wid & 1) * 16;
    const int tg   = wid >> 1;
    const int wn8  = tg * 8;
    const int wn32 = tg * 32;
    const int a_r = lane & 15, a_cB = (lane >> 4) << 4;
    const int b_r = lane & 7,  b_cB = ((lane >> 3) & 1) << 4;
    const int fr = lane >> 2, fc = (lane & 3) * 2;

    float wnr[2];
#pragma unroll
    for (int pp = 0; pp < 2; pp++)
        wnr[pp] = wnorm[dvq * 32 + wm + pp * 8 + fr];

    for (int c = 0; c < NC_; c++) {
        const size_t ch = (size_t)bh * NC_ + c;
        const int cb = c & 1;
        const uint32_t ob = sb + OS_OPS + cb * OB_SIZE;
        float* W0s = (float*)(smraw + OS_OPS + cb * OB_SIZE + OB_W0);

        __syncthreads();
        if (c + 1 < NC_)
            seq_load_ops(sb + OS_OPS + (1 - cb) * OB_SIZE, ch + 1, dvq, tid,
                         W0g, TKh, TKl, Qh, Ql, KTh, KTl, Ph, Pl);
        else
            CP_COMMIT();
        CP_WAIT(1);
        __syncthreads();

        // ---- fused S-sweep: acc = Ssm @ TK^T, oacc = Ssm @ Q^T (shared ah/al) ----
        float acc[4], oacc[4];
#pragma unroll
        for (int e = 0; e < 4; e++) { acc[e] = 0.f; oacc[e] = 0.f; }
#pragma unroll
        for (int ks = 0; ks < 8; ks++) {
            uint32_t ah[4], al[4], bt_h[2], bt_l[2], bq_h[2], bq_l[2];
            uint32_t offa = (wm + a_r) * SST + a_cB + ks * 32;
            LDSM_X4(ah[0], ah[1], ah[2], ah[3], sb + OS_SHI + offa);
            LDSM_X4(al[0], al[1], al[2], al[3], sb + OS_SLO + offa);
            uint32_t offb = (wn8 + b_r) * SST + b_cB + ks * 32;
            LDSM_X2(bt_h[0], bt_h[1], ob + OB_TKH + offb);
            LDSM_X2(bt_l[0], bt_l[1], ob + OB_TKL + offb);
            LDSM_X2(bq_h[0], bq_h[1], ob + OB_QH + offb);
            LDSM_X2(bq_l[0], bq_l[1], ob + OB_QL + offb);
            mma_bf16(acc,  ah, bt_h);
            mma_bf16(acc,  ah, bt_l);
            mma_bf16(acc,  al, bt_h);
            mma_bf16(oacc, ah, bq_h);
            mma_bf16(oacc, ah, bq_l);
            mma_bf16(oacc, al, bq_h);
        }
        // Wt = W0^T - acc  -> smem (hi/lo)
#pragma unroll
        for (int pp = 0; pp < 2; pp++) {
            int m = wm + fr + pp * 8;
            int n0 = wn8 + fc;
            float v0 = W0s[n0 * 32 + m] - acc[pp * 2 + 0];
            float v1 = W0s[(n0 + 1) * 32 + m] - acc[pp * 2 + 1];
            uint32_t lo, hi = pack_split(v0, v1, lo);
            *(uint32_t*)(smraw + OS_WTH + m * WST + n0 * 2) = hi;
            *(uint32_t*)(smraw + OS_WTL + m * WST + n0 * 2) = lo;
        }
        __syncthreads();

        // ---- fused Wt-sweep: Ot += Wt @ P^T  AND  Ssm += Wt @ K (shared ah/al) ----
#pragma unroll
        for (int ks = 0; ks < 2; ks++) {
            uint32_t ah[4], al[4], bp_h[2], bp_l[2];
            uint32_t offa = (wm + a_r) * WST + a_cB + ks * 32;
            LDSM_X4(ah[0], ah[1], ah[2], ah[3], sb + OS_WTH + offa);
            LDSM_X4(al[0], al[1], al[2], al[3], sb + OS_WTL + offa);
            uint32_t offp = (wn8 + b_r) * WST + b_cB + ks * 32;
            LDSM_X2(bp_h[0], bp_h[1], ob + OB_PH + offp);
            LDSM_X2(bp_l[0], bp_l[1], ob + OB_PL + offp);
            mma_bf16(oacc, ah, bp_h);
            mma_bf16(oacc, ah, bp_l);
            mma_bf16(oacc, al, bp_h);
#pragma unroll
            for (int ni = 0; ni < 4; ni++) {
                uint32_t bk_h[2], bk_l[2];
                uint32_t offk = (wn32 + ni * 8 + b_r) * WST + b_cB + ks * 32;
                LDSM_X2(bk_h[0], bk_h[1], ob + OB_KTH + offk);
                LDSM_X2(bk_l[0], bk_l[1], ob + OB_KTL + offk);
                mma_bf16(Sfr[ni], ah, bk_h);
                mma_bf16(Sfr[ni], ah, bk_l);
                mma_bf16(Sfr[ni], al, bk_h);
            }
        }

        // colsum partials (after oacc complete)
        {
            float s0 = oacc[0] * oacc[0] + oacc[2] * oacc[2];
            float s1 = oacc[1] * oacc[1] + oacc[3] * oacc[3];
#pragma unroll
            for (int off = 4; off <= 16; off <<= 1) {
                s0 += __shfl_xor_sync(0xffffffffu, s0, off);
                s1 += __shfl_xor_sync(0xffffffffu, s1, off);
            }
            if (lane < 4) {
                atomicAdd(&colsum[cb * 32 + wn8 + 2 * lane], s0);
                atomicAdd(&colsum[cb * 32 + wn8 + 2 * lane + 1], s1);
            }
        }

        // pack S -> smem for next chunk (safe: S smem next read after 2 barriers)
#pragma unroll
        for (int ni = 0; ni < 4; ni++)
#pragma unroll
            for (int pp = 0; pp < 2; pp++) {
                int m = wm + fr + pp * 8;
                int n0 = wn32 + ni * 8 + fc;
                uint32_t lo, hi = pack_split(Sfr[ni][pp * 2], Sfr[ni][pp * 2 + 1], lo);
                *(uint32_t*)(smraw + OS_SHI + m * SST + n0 * 2) = hi;
                *(uint32_t*)(smraw + OS_SLO + m * SST + n0 * 2) = lo;
            }
        __syncthreads();   // colsum complete before read

        // o-store + oss publish + zero other colsum
        {
            const size_t obase = (size_t)b * L_ * D_ + (size_t)h * DH_ + (size_t)(c * C_) * D_
                               + dvq * 32;
            int n0 = wn8 + fc;
#pragma unroll
            for (int pp = 0; pp < 2; pp++) {
                int m = wm + fr + pp * 8;
                o[obase + (size_t)n0 * D_ + m] = oacc[pp * 2] * wnr[pp];
                o[obase + (size_t)(n0 + 1) * D_ + m] = oacc[pp * 2 + 1] * wnr[pp];
            }
            if (tid < 32) {
                oss[(size_t)dvq * (M_ * H_) + ((size_t)b * L_ + c * C_ + tid) * H_ + h]
                    = colsum[cb * 32 + tid];
                colsum[(1 - cb) * 32 + tid] = 0.f;
            }
        }
    }
}

// ================= launch =================
extern "C" void kernel_launch(void* const* d_in, const int* in_sizes, int n_in,
                              void* d_out, int out_size) {
    const float* X  = (const float*)d_in[0];
    const float* Wq = (const float*)d_in[1];
    const float* Wk = (const float*)d_in[2];
    const float* Wv = (const float*)d_in[3];
    const float* Wb = (const float*)d_in[4];
    const float* wn = (const float*)d_in[5];
    const float* Wo = (const float*)d_in[6];
    float* out = (float*)d_out;

    float *gq, *gk, *gv, *go, *gb, *gW0, *gss;
    __half *ahi, *wt;
    __nv_bfloat16 *tkh, *tkl, *qch, *qcl, *kth, *ktl, *ph, *pl;
    cudaGetSymbolAddress((void**)&gq, g_q);
    cudaGetSymbolAddress((void**)&gk, g_k);
    cudaGetSymbolAddress((void**)&gv, g_v);
    cudaGetSymbolAddress((void**)&go, g_o);
    cudaGetSymbolAddress((void**)&gb, g_beta);
    cudaGetSymbolAddress((void**)&gss, g_ss);
    cudaGetSymbolAddress((void**)&ahi, g_Ahi);
    cudaGetSymbolAddress((void**)&wt, g_Wt);
    cudaGetSymbolAddress((void**)&gW0, g_W0);
    cudaGetSymbolAddress((void**)&tkh, g_TKh);
    cudaGetSymbolAddress((void**)&tkl, g_TKl);
    cudaGetSymbolAddress((void**)&qch, g_Qch);
    cudaGetSymbolAddress((void**)&qcl, g_Qcl);
    cudaGetSymbolAddress((void**)&kth, g_KTh);
    cudaGetSymbolAddress((void**)&ktl, g_KTl);
    cudaGetSymbolAddress((void**)&ph, g_Ph);
    cudaGetSymbolAddress((void**)&pl, g_Pl);

    cudaFuncSetAttribute(gemm_f16, cudaFuncAttributeMaxDynamicSharedMemorySize, SMEM_DYN);
    cudaFuncSetAttribute(pre_chunk, cudaFuncAttributeMaxDynamicSharedMemorySize, 69760);
    cudaFuncSetAttribute(seq_chunk, cudaFuncAttributeMaxDynamicSharedMemorySize, SEQ_SMEM);

    const int NSPLIT = M_ * D_ / 4 / 256;

    split_rows<<<NSPLIT, 256>>>((const float4*)X, (uint2*)ahi);
    split_transpose<<<dim3(D_ / 32, D_ / 32, 4), dim3(32, 8)>>>(Wq, Wk, Wv, Wo, wt);

    GemmArgs qa;
    qa.Bw[0] = wt;
    qa.Bw[1] = wt + (size_t)D_ * D_;
    qa.Bw[2] = wt + (size_t)2 * D_ * D_;
    qa.C[0] = gq; qa.C[1] = gk; qa.C[2] = gv;
    qa.mode[0] = 0; qa.mode[1] = 0; qa.mode[2] = 1;
    gemm_f16<<<dim3(D_ / BN, M_ / BM, 3), 256, SMEM_DYN>>>(ahi, qa);

    beta_gemm<<<M_ / 16, 256>>>(X, Wb, gb);

    pre_chunk<<<NCH_, 128, 69760>>>(gq, gk, gv, gb, gW0, tkh, tkl, qch, qcl, kth, ktl, ph, pl);
    seq_chunk<<<4 * B_ * H_, 256, SEQ_SMEM>>>(gW0, tkh, tkl, qch, qcl, kth, ktl, ph, pl, wn, go, gss);

    split_rows_norm<<<NSPLIT, 256>>>((const float4*)go, (uint2*)ahi, gss);
    GemmArgs oa;
    oa.Bw[0] = wt + (size_t)3 * D_ * D_;
    oa.Bw[1] = oa.Bw[0];
    oa.Bw[2] = oa.Bw[0];
    oa.C[0] = out; oa.C[1] = out; oa.C[2] = out;
    oa.mode[0] = 0; oa.mode[1] = 0; oa.mode[2] = 0;
    gemm_f16<<<dim3(D_ / BN, M_ / BM, 1), 256, SMEM_DYN>>>(ahi, oa);
}